// round 8
// baseline (speedup 1.0000x reference)
#include <cuda_runtime.h>

#define B   8
#define CI  32
#define CO  32
#define NY  128
#define NX  128
#define M1  4
#define M2  5

#define TWO_PI_F 6.283185307179586476925f

typedef unsigned long long ull;

__device__ __forceinline__ float2 cmul(float2 a, float2 b) {
    return make_float2(a.x*b.x - a.y*b.y, a.x*b.y + a.y*b.x);
}
__device__ __forceinline__ float2 cfma(float2 a, float2 b, float2 c) {
    c.x = fmaf(a.x, b.x, fmaf(-a.y, b.y, c.x));
    c.y = fmaf(a.x, b.y, fmaf( a.y, b.x, c.y));
    return c;
}
__device__ __forceinline__ ull pack2(float lo, float hi) {
    ull r; asm("mov.b64 %0, {%1, %2};" : "=l"(r) : "f"(lo), "f"(hi)); return r;
}
__device__ __forceinline__ float2 unpack2(ull v) {
    float2 f; asm("mov.b64 {%0, %1}, %2;" : "=f"(f.x), "=f"(f.y) : "l"(v)); return f;
}
__device__ __forceinline__ ull fma2(ull a, ull b, ull c) {
    ull d; asm("fma.rn.f32x2 %0, %1, %2, %3;" : "=l"(d) : "l"(a), "l"(b), "l"(c)); return d;
}
__device__ __forceinline__ ull swap2(ull a) {
    float2 f = unpack2(a);
    return pack2(f.y, f.x);
}

// ---------------- scratch ---------------------------------------------------
__device__ float2 g_tmp  [B*CI*NY*NX];
__device__ float2 g_alpha[B*CI*NY*NX];
__device__ float2 g_A1   [CI*CO*M1*NY];
__device__ float2 g_A2   [CI*CO*M2*NX];
__device__ float2 g_E1   [CI*CO*M1*NY];
__device__ float2 g_E2   [CI*CO*M2*NX];
__device__ float2 g_H    [CI*CO*NY*NX];
__device__ float2 g_T2   [B*CI*CO*M2*NY];
__device__ float2 g_res2 [B*CO*M1*M2];
__device__ float2 g_G    [B*CI*CO*M2*NY];

__device__ __forceinline__ void make_tws(float2* tws, int t) {
    if (t < 64) {
        float sn, cs;
        sincospif(-(float)t / 64.f, &sn, &cs);
        tws[t] = make_float2(cs, sn);
    }
}

// ---------------- merged pole factors (launch 0) ----------------------------
__global__ void k_fac(const float* __restrict__ wp1_re, const float* __restrict__ wp1_im,
                      const float* __restrict__ wp2_re, const float* __restrict__ wp2_im,
                      const float* __restrict__ ty, const float* __restrict__ tx) {
    int blk = blockIdx.x;
    int o   = threadIdx.x;
    if (blk < CI*CO*M1) {
        int ikp = blk;
        float wr = wp1_re[ikp], wi = wp1_im[ikp];
        float d = ty[1] - ty[0];
        float invnd = 1.0f / ((float)NY * d);
        float k = (o < NY/2) ? (float)o : (float)(o - NY);
        float lam = TWO_PI_F * k * invnd;
        float a = -wr, b = lam - wi;
        float inv = 1.0f / (a*a + b*b);
        g_A1[ikp*NY + o] = make_float2(a*inv, -b*inv);
        float t = ty[o];
        float e = expf(wr * t);
        float sn, cs; sincosf(wi * t, &sn, &cs);
        g_E1[ikp*NY + o] = make_float2(e*cs, e*sn);
    } else {
        int ikq = blk - CI*CO*M1;
        float wr = wp2_re[ikq], wi = wp2_im[ikq];
        float d = tx[1] - tx[0];
        float invnd = 1.0f / ((float)NX * d);
        float k = (o < NX/2) ? (float)o : (float)(o - NX);
        float lam = TWO_PI_F * k * invnd;
        float a = -wr, b = lam - wi;
        float inv = 1.0f / (a*a + b*b);
        g_A2[ikq*NX + o] = make_float2(a*inv, -b*inv);
        float t = tx[o];
        float e = expf(wr * t);
        float sn, cs; sincosf(wi * t, &sn, &cs);
        g_E2[ikq*NX + o] = make_float2(e*cs, e*sn);
    }
}

// ---------------- 128-pt radix-2 DIT ----------------------------------------
template<int INV>
__device__ __forceinline__ void fft64th(float2* s, int tt, const float2* tws) {
    #pragma unroll
    for (int stage = 1; stage <= 7; stage++) {
        __syncthreads();
        int half = 1 << (stage - 1);
        int p  = tt & (half - 1);
        int i0 = ((tt >> (stage - 1)) << stage) + p;
        int i1 = i0 + half;
        float2 w = tws[p << (7 - stage)];
        float wy = INV ? -w.y : w.y;
        float2 u = s[i0], v0 = s[i1];
        float2 v = make_float2(v0.x*w.x - v0.y*wy, v0.x*wy + v0.y*w.x);
        s[i0] = make_float2(u.x + v.x, u.y + v.y);
        s[i1] = make_float2(u.x - v.x, u.y - v.y);
    }
}

// forward FFT of real rows (launch 1)
__global__ void k_fft_rows_f(const float* __restrict__ x) {
    __shared__ float2 s[2][NX];
    __shared__ float2 tws[64];
    int t = threadIdx.x, r = t >> 6, tt = t & 63;
    make_tws(tws, t);
    size_t row = (size_t)blockIdx.x * 2 + r;
    const float* xr = x + row * NX;
    s[r][tt]      = make_float2(xr[__brev(tt)      >> 25], 0.f);
    s[r][tt + 64] = make_float2(xr[__brev(tt + 64) >> 25], 0.f);
    fft64th<0>(s[r], tt, tws);
    float2* o = g_tmp + row * NX;
    o[tt] = s[r][tt]; o[tt + 64] = s[r][tt + 64];
}

template<int INV>
__device__ __forceinline__ void fft_col(float2 (*tile)[17], int tg, int tx, const float2* tws) {
    #pragma unroll
    for (int stage = 1; stage <= 7; stage++) {
        __syncthreads();
        int half = 1 << (stage - 1);
        #pragma unroll
        for (int m = 0; m < 8; m++) {
            int j  = tg + 8 * m;
            int p  = j & (half - 1);
            int i0 = ((j >> (stage - 1)) << stage) + p;
            int i1 = i0 + half;
            float2 w = tws[p << (7 - stage)];
            float wy = INV ? -w.y : w.y;
            float2 u = tile[i0][tx], v0 = tile[i1][tx];
            float2 v = make_float2(v0.x*w.x - v0.y*wy, v0.x*wy + v0.y*w.x);
            tile[i0][tx] = make_float2(u.x + v.x, u.y + v.y);
            tile[i1][tx] = make_float2(u.x - v.x, u.y - v.y);
        }
    }
}

// forward columns (launch 2): g_tmp -> g_alpha
__global__ void k_fft_cols_f() {
    __shared__ float2 tile[NY][17];
    __shared__ float2 tws[64];
    int t = threadIdx.x;
    make_tws(tws, t);
    int blk = blockIdx.x;
    int xt = blk & 7, img = blk >> 3;
    int x0 = xt * 16;
    int tg = t >> 4, tx = t & 15;
    const float2* base = g_tmp + (size_t)img * NY * NX + x0;
    #pragma unroll
    for (int c = 0; c < 16; c++) {
        int y = c * 8 + tg;
        tile[__brev(y) >> 25][tx] = base[(size_t)y * NX + tx];
    }
    fft_col<0>(tile, tg, tx, tws);
    __syncthreads();
    float2* ob = g_alpha + (size_t)img * NY * NX + x0;
    #pragma unroll
    for (int c = 0; c < 16; c++) {
        int y = c * 8 + tg;
        ob[(size_t)y * NX + tx] = tile[y][tx];
    }
}

// ---------------- T2: LDS.128 two-accumulator complex GEMM (launch 3) -------
// even pitch 130 -> ulonglong2 loads, conflict-free (stride ≡ 4 mod 32,
// 8-lane phases each cover banks 0..31 exactly once).
#define T2_OT 64
#define T2_KC 40
#define T2_PITCH 130
#define T2_SMEM ((T2_OT + T2_KC) * T2_PITCH * sizeof(float2))
extern __shared__ float2 t2sm[];
__global__ void __launch_bounds__(256, 2) k_T2() {
    float2* alphaS = t2sm;                      // [64 o][130 x]
    float2* a2S    = t2sm + T2_OT*T2_PITCH;     // [40 kq][130 x]
    const ulonglong2* alphaQ = (const ulonglong2*)alphaS;   // pitch 65
    const ulonglong2* a2Q    = (const ulonglong2*)a2S;
    int blk = blockIdx.x;
    int oh = blk & 1;
    int bi = blk >> 1;
    int i  = bi & 31;
    int o0 = oh * T2_OT;
    int t  = threadIdx.x;
    const float2* A = g_alpha + (size_t)bi * NY * NX + (size_t)o0 * NX;
    #pragma unroll 4
    for (int l = t; l < T2_OT*128; l += 256) {
        int o = l >> 7, x = l & 127;
        alphaS[o*T2_PITCH + x] = A[(size_t)o * NX + x];
    }
    int u = t >> 5, v = t & 31;
    #pragma unroll 1
    for (int c = 0; c < 4; c++) {
        int kq0 = c * T2_KC;
        __syncthreads();
        for (int l = t; l < T2_KC*128; l += 256) {
            int r = l >> 7, x = l & 127;
            a2S[r*T2_PITCH + x] = g_A2[(size_t)(i*CO*M2 + kq0 + r) * NX + x];
        }
        __syncthreads();
        ull accP[5][2], accQ[5][2];
        #pragma unroll
        for (int j = 0; j < 5; j++)
            #pragma unroll
            for (int m = 0; m < 2; m++) {
                accP[j][m] = pack2(0.f, 0.f);
                accQ[j][m] = pack2(0.f, 0.f);
            }
        #pragma unroll 2
        for (int xp = 0; xp < 64; xp++) {
            ulonglong2 bv[5];
            #pragma unroll
            for (int j = 0; j < 5; j++)
                bv[j] = a2Q[(u*5 + j)*65 + xp];
            #pragma unroll
            for (int m = 0; m < 2; m++) {
                ulonglong2 av = alphaQ[(v + 32*m)*65 + xp];
                ull a0 = av.x, a1 = av.y;
                ull s0 = swap2(a0), s1 = swap2(a1);
                #pragma unroll
                for (int j = 0; j < 5; j++) {
                    accP[j][m] = fma2(a0, bv[j].x, accP[j][m]);
                    accQ[j][m] = fma2(s0, bv[j].x, accQ[j][m]);
                    accP[j][m] = fma2(a1, bv[j].y, accP[j][m]);
                    accQ[j][m] = fma2(s1, bv[j].y, accQ[j][m]);
                }
            }
        }
        #pragma unroll
        for (int j = 0; j < 5; j++) {
            float2* dst = g_T2 + ((size_t)bi * CO*M2 + kq0 + u*5 + j) * NY + o0;
            #pragma unroll
            for (int m = 0; m < 2; m++) {
                float2 p = unpack2(accP[j][m]);
                float2 q = unpack2(accQ[j][m]);
                dst[v + 32*m] = make_float2(p.x - p.y, q.x + q.y);
            }
        }
    }
}

// ---------------- res2[b,k,p,q] = sum_i wr * sum_o A1[p,o]*T2[q,o] ---------
__global__ void k_res2(const float* __restrict__ wr_re, const float* __restrict__ wr_im) {
    int bk = blockIdx.x;
    int b = bk >> 5, k = bk & 31;
    int t = threadIdx.x;
    __shared__ float2 wrS[CI][M1*M2];
    for (int idx = t; idx < CI*M1*M2; idx += 128) {
        int i = idx / (M1*M2), pq = idx % (M1*M2);
        wrS[i][pq] = make_float2(wr_re[(i*CO + k)*M1*M2 + pq], wr_im[(i*CO + k)*M1*M2 + pq]);
    }
    __syncthreads();
    float2 acc[M1*M2];
    #pragma unroll
    for (int j = 0; j < M1*M2; j++) acc[j] = make_float2(0.f, 0.f);
    for (int i = 0; i < CI; i++) {
        float2 a1[M1], t2[M2];
        #pragma unroll
        for (int p = 0; p < M1; p++) a1[p] = g_A1[((i*CO + k)*M1 + p)*NY + t];
        #pragma unroll
        for (int q = 0; q < M2; q++) t2[q] = g_T2[(((size_t)(b*CI + i)*CO + k)*M2 + q)*NY + t];
        #pragma unroll
        for (int p = 0; p < M1; p++)
            #pragma unroll
            for (int q = 0; q < M2; q++) {
                float2 wa = cmul(wrS[i][p*M2 + q], a1[p]);
                acc[p*M2 + q] = cfma(wa, t2[q], acc[p*M2 + q]);
            }
    }
    #pragma unroll
    for (int j = 0; j < M1*M2; j++)
        #pragma unroll
        for (int off = 16; off; off >>= 1) {
            acc[j].x += __shfl_down_sync(0xffffffffu, acc[j].x, off);
            acc[j].y += __shfl_down_sync(0xffffffffu, acc[j].y, off);
        }
    __shared__ float2 red[4][M1*M2];
    int w = t >> 5, lane = t & 31;
    if (lane == 0) {
        #pragma unroll
        for (int j = 0; j < M1*M2; j++) red[w][j] = acc[j];
    }
    __syncthreads();
    if (t < M1*M2) {
        float2 s = red[0][t];
        #pragma unroll
        for (int w2 = 1; w2 < 4; w2++) { s.x += red[w2][t].x; s.y += red[w2][t].y; }
        g_res2[bk*M1*M2 + t] = s;
    }
}

// ---------------- G[b,c,k,q,z] = sum_p res2[b,c,p,q] * E1[c,k,p,z] ---------
__global__ void k_G() {
    int blk = blockIdx.x;
    int b = blk >> 10, c = (blk >> 5) & 31, k = blk & 31;
    int z = threadIdx.x;
    __shared__ float2 r2[M1*M2];
    if (z < M1*M2) r2[z] = g_res2[(b*CO + c)*M1*M2 + z];
    __syncthreads();
    float2 e1[M1];
    #pragma unroll
    for (int p = 0; p < M1; p++) e1[p] = g_E1[((c*CO + k)*M1 + p)*NY + z];
    #pragma unroll
    for (int q = 0; q < M2; q++) {
        float2 acc = make_float2(0.f, 0.f);
        #pragma unroll
        for (int p = 0; p < M1; p++) acc = cfma(r2[p*M2 + q], e1[p], acc);
        g_G[(((size_t)(b*CI + c)*CO + k)*M2 + q)*NY + z] = acc;
    }
}

// ---------------- Hsum full (streaming stores) ------------------------------
__global__ void k_hsum(const float* __restrict__ wr_re, const float* __restrict__ wr_im) {
    int ik = blockIdx.x;
    int t  = threadIdx.x;
    __shared__ float2 wrS[M1*M2];
    __shared__ float2 A1S[M1][NY];
    __shared__ float2 U[M2][NY];
    if (t < M1*M2) wrS[t] = make_float2(wr_re[ik*M1*M2 + t], wr_im[ik*M1*M2 + t]);
    #pragma unroll
    for (int p = 0; p < M1; p++) A1S[p][t] = g_A1[(ik*M1 + p)*NY + t];
    float2 a2[M2];
    #pragma unroll
    for (int q = 0; q < M2; q++) a2[q] = g_A2[(ik*M2 + q)*NX + t];
    __syncthreads();
    #pragma unroll
    for (int q = 0; q < M2; q++) {
        float2 acc = make_float2(0.f, 0.f);
        #pragma unroll
        for (int p = 0; p < M1; p++) acc = cfma(wrS[p*M2 + q], A1S[p][t], acc);
        U[q][t] = acc;
    }
    __syncthreads();
    float2* H = g_H + (size_t)ik * NY * NX;
    for (int o = 0; o < NY; o++) {
        float2 acc = make_float2(0.f, 0.f);
        #pragma unroll
        for (int q = 0; q < M2; q++) acc = cfma(U[q][o], a2[q], acc);
        __stcs(&H[o*NX + t], acc);
    }
}

// ---------------- res1 fused with inverse row FFT; prefetched ---------------
__global__ void __launch_bounds__(128, 3) k_res1f() {
    __shared__ float2 rows[32][129];
    __shared__ float2 tws[64];
    int o  = blockIdx.x & 127;
    int k0 = (blockIdx.x >> 7) * 4;
    int x  = threadIdx.x;
    make_tws(tws, x);
    ull acc[4][B];
    #pragma unroll
    for (int kk = 0; kk < 4; kk++)
        #pragma unroll
        for (int b = 0; b < B; b++) acc[kk][b] = pack2(0.f, 0.f);

    // prefetch i = 0
    float2 hc[4], ac[8];
    #pragma unroll
    for (int kk = 0; kk < 4; kk++)
        hc[kk] = __ldcs(&g_H[((size_t)(0*CO + k0 + kk) * NY + o) * NX + x]);
    #pragma unroll
    for (int b = 0; b < B; b++)
        ac[b] = g_alpha[((size_t)(b*CI + 0) * NY + o) * NX + x];

    for (int i = 0; i < CI; i++) {
        float2 hn[4], an[8];
        if (i + 1 < CI) {
            #pragma unroll
            for (int kk = 0; kk < 4; kk++)
                hn[kk] = __ldcs(&g_H[((size_t)((i+1)*CO + k0 + kk) * NY + o) * NX + x]);
            #pragma unroll
            for (int b = 0; b < B; b++)
                an[b] = g_alpha[((size_t)(b*CI + i + 1) * NY + o) * NX + x];
        }
        ull hxx[4], hpm[4];
        #pragma unroll
        for (int kk = 0; kk < 4; kk++) {
            hxx[kk] = pack2(hc[kk].x,  hc[kk].x);
            hpm[kk] = pack2(-hc[kk].y, hc[kk].y);
        }
        #pragma unroll
        for (int b = 0; b < B; b++) {
            ull au = pack2(ac[b].x, ac[b].y);
            ull as = pack2(ac[b].y, ac[b].x);
            #pragma unroll
            for (int kk = 0; kk < 4; kk++) {
                acc[kk][b] = fma2(au, hxx[kk], acc[kk][b]);
                acc[kk][b] = fma2(as, hpm[kk], acc[kk][b]);
            }
        }
        if (i + 1 < CI) {
            #pragma unroll
            for (int kk = 0; kk < 4; kk++) hc[kk] = hn[kk];
            #pragma unroll
            for (int b = 0; b < B; b++) ac[b] = an[b];
        }
    }
    int xr = __brev(x) >> 25;
    #pragma unroll
    for (int kk = 0; kk < 4; kk++)
        #pragma unroll
        for (int b = 0; b < B; b++)
            rows[kk*8 + b][xr] = unpack2(acc[kk][b]);
    __syncthreads();
    #pragma unroll
    for (int stage = 1; stage <= 7; stage++) {
        int half = 1 << (stage - 1);
        #pragma unroll
        for (int m = 0; m < 16; m++) {
            int l = x + 128*m;
            int r = l >> 6, j = l & 63;
            int p = j & (half - 1);
            int i0 = ((j >> (stage - 1)) << stage) + p;
            int i1 = i0 + half;
            float2 w = tws[p << (7 - stage)];
            float2 u = rows[r][i0], v0 = rows[r][i1];
            float2 v = make_float2(v0.x*w.x + v0.y*w.y, -v0.x*w.y + v0.y*w.x);
            rows[r][i0] = make_float2(u.x + v.x, u.y + v.y);
            rows[r][i1] = make_float2(u.x - v.x, u.y - v.y);
        }
        __syncthreads();
    }
    #pragma unroll
    for (int kk = 0; kk < 4; kk++)
        #pragma unroll
        for (int b = 0; b < B; b++)
            g_tmp[(((size_t)(b*CO + k0 + kk)) * NY + o) * NX + x] = rows[kk*8 + b][x];
}

// inverse columns + real part + scale: g_tmp -> out
__global__ void k_ifft_cols_r(float* __restrict__ out) {
    __shared__ float2 tile[NY][17];
    __shared__ float2 tws[64];
    int t = threadIdx.x;
    make_tws(tws, t);
    int blk = blockIdx.x;
    int xt = blk & 7, img = blk >> 3;
    int x0 = xt * 16;
    int tg = t >> 4, tx = t & 15;
    const float2* base = g_tmp + (size_t)img * NY * NX + x0;
    #pragma unroll
    for (int c = 0; c < 16; c++) {
        int y = c * 8 + tg;
        tile[__brev(y) >> 25][tx] = base[(size_t)y * NX + tx];
    }
    fft_col<1>(tile, tg, tx, tws);
    __syncthreads();
    const float INV = 1.0f / (float)(NY * NX);
    float* ob = out + (size_t)img * NY * NX + x0;
    #pragma unroll
    for (int c = 0; c < 16; c++) {
        int y = c * 8 + tg;
        ob[(size_t)y * NX + tx] = tile[y][tx].x * INV;
    }
}

// ---------------- x2: out += Re( G[z,cq] * E2[cq,x] ) / (NY*NX) ------------
// raw-raw packed accumulation: acc += {gx·ex, gy·ey}; result = lo - hi.
__global__ void __launch_bounds__(256, 2) k_x2(float* __restrict__ out) {
    __shared__ float2 Gs[16][66];         // even pitch -> 16B-aligned pairs
    __shared__ float2 Es[16][129];
    int blk = blockIdx.x;
    int zh  = blk & 1;
    int bk  = blk >> 1;
    int b = bk >> 5, k = bk & 31;
    int z0 = zh * 64;
    int t = threadIdx.x;
    int u = t >> 5, v = t & 31;
    ull acc[8][4];
    #pragma unroll
    for (int j = 0; j < 8; j++)
        #pragma unroll
        for (int m = 0; m < 4; m++) acc[j][m] = pack2(0.f, 0.f);
    for (int k0 = 0; k0 < CI*M2; k0 += 16) {
        __syncthreads();
        for (int l = t; l < 16*64; l += 256) {
            int r = l >> 6, zz = l & 63;
            int cq = k0 + r; int c = cq / M2, q = cq % M2;
            Gs[r][zz] = g_G[(((size_t)(b*CI + c)*CO + k)*M2 + q)*NY + z0 + zz];
        }
        for (int l = t; l < 16*128; l += 256) {
            int r = l >> 7, xx = l & 127;
            int cq = k0 + r; int c = cq / M2, q = cq % M2;
            Es[r][xx] = g_E2[((size_t)(c*CO + k)*M2 + q)*NX + xx];
        }
        __syncthreads();
        #pragma unroll
        for (int kk = 0; kk < 16; kk++) {
            ulonglong2 gp[4];
            const ulonglong2* gq = (const ulonglong2*)&Gs[kk][u*8];
            #pragma unroll
            for (int jp = 0; jp < 4; jp++) gp[jp] = gq[jp];
            #pragma unroll
            for (int m = 0; m < 4; m++) {
                ull e = *(const ull*)&Es[kk][v + 32*m];
                #pragma unroll
                for (int jp = 0; jp < 4; jp++) {
                    acc[2*jp  ][m] = fma2(gp[jp].x, e, acc[2*jp  ][m]);
                    acc[2*jp+1][m] = fma2(gp[jp].y, e, acc[2*jp+1][m]);
                }
            }
        }
    }
    const float INV = 1.0f / (float)(NY * NX);
    float* ob = out + (size_t)(b*CO + k) * NY * NX;
    #pragma unroll
    for (int j = 0; j < 8; j++) {
        int z = z0 + u*8 + j;
        #pragma unroll
        for (int m = 0; m < 4; m++) {
            float2 r = unpack2(acc[j][m]);
            ob[(size_t)z * NX + v + 32*m] += (r.x - r.y) * INV;
        }
    }
}

// ---------------------------------------------------------------------------
extern "C" void kernel_launch(void* const* d_in, const int* in_sizes, int n_in,
                              void* d_out, int out_size) {
    const float* x      = (const float*)d_in[0];
    const float* wp1_re = (const float*)d_in[1];
    const float* wp1_im = (const float*)d_in[2];
    const float* wp2_re = (const float*)d_in[3];
    const float* wp2_im = (const float*)d_in[4];
    const float* wr_re  = (const float*)d_in[5];
    const float* wr_im  = (const float*)d_in[6];
    const float* ty     = (const float*)d_in[7];
    const float* tx     = (const float*)d_in[8];
    float* out = (float*)d_out;

    cudaFuncSetAttribute(k_T2, cudaFuncAttributeMaxDynamicSharedMemorySize, (int)T2_SMEM);

    k_fac         <<<CI*CO*(M1+M2), 128>>>(wp1_re, wp1_im, wp2_re, wp2_im, ty, tx);  // 0
    k_fft_rows_f  <<<B*CI*NY/2, 128>>>(x);                                           // 1
    k_fft_cols_f  <<<B*CI*8, 128>>>();                                               // 2
    k_T2          <<<B*CI*2, 256, T2_SMEM>>>();                                      // 3 (profiled)
    k_res2        <<<B*CO, 128>>>(wr_re, wr_im);                                     // 4
    k_G           <<<B*CI*CO, 128>>>();                                              // 5
    k_hsum        <<<CI*CO, 128>>>(wr_re, wr_im);                                    // 6
    k_res1f       <<<8*NY, 128>>>();                                                 // 7
    k_ifft_cols_r <<<B*CO*8, 128>>>(out);                                            // 8
    k_x2          <<<B*CO*2, 256>>>(out);                                            // 9
}

// round 9
// speedup vs baseline: 1.0133x; 1.0133x over previous
#include <cuda_runtime.h>

#define B   8
#define CI  32
#define CO  32
#define NY  128
#define NX  128
#define M1  4
#define M2  5

#define TWO_PI_F 6.283185307179586476925f

typedef unsigned long long ull;

__device__ __forceinline__ float2 cmul(float2 a, float2 b) {
    return make_float2(a.x*b.x - a.y*b.y, a.x*b.y + a.y*b.x);
}
__device__ __forceinline__ float2 cfma(float2 a, float2 b, float2 c) {
    c.x = fmaf(a.x, b.x, fmaf(-a.y, b.y, c.x));
    c.y = fmaf(a.x, b.y, fmaf( a.y, b.x, c.y));
    return c;
}
__device__ __forceinline__ ull pack2(float lo, float hi) {
    ull r; asm("mov.b64 %0, {%1, %2};" : "=l"(r) : "f"(lo), "f"(hi)); return r;
}
__device__ __forceinline__ float2 unpack2(ull v) {
    float2 f; asm("mov.b64 {%0, %1}, %2;" : "=f"(f.x), "=f"(f.y) : "l"(v)); return f;
}
__device__ __forceinline__ ull fma2(ull a, ull b, ull c) {
    ull d; asm("fma.rn.f32x2 %0, %1, %2, %3;" : "=l"(d) : "l"(a), "l"(b), "l"(c)); return d;
}
__device__ __forceinline__ ull swap2(ull a) {
    float2 f = unpack2(a);
    return pack2(f.y, f.x);
}

// ---------------- scratch ---------------------------------------------------
__device__ float2 g_tmp  [B*CI*NY*NX];
__device__ float2 g_alpha[B*CI*NY*NX];
__device__ float2 g_A1   [CI*CO*M1*NY];
__device__ float2 g_A2   [CI*CO*M2*NX];
__device__ float2 g_E1   [CI*CO*M1*NY];
__device__ float2 g_E2   [CI*CO*M2*NX];
__device__ float2 g_H    [CI*CO*NY*NX];
__device__ float2 g_T2   [B*CI*CO*M2*NY];
__device__ float2 g_res2 [B*CO*M1*M2];
__device__ float2 g_G    [B*CI*CO*M2*NY];

__device__ __forceinline__ void make_tws(float2* tws, int t) {
    if (t < 64) {
        float sn, cs;
        sincospif(-(float)t / 64.f, &sn, &cs);
        tws[t] = make_float2(cs, sn);
    }
}

// ---------------- merged pole factors (launch 0) ----------------------------
__global__ void k_fac(const float* __restrict__ wp1_re, const float* __restrict__ wp1_im,
                      const float* __restrict__ wp2_re, const float* __restrict__ wp2_im,
                      const float* __restrict__ ty, const float* __restrict__ tx) {
    int blk = blockIdx.x;
    int o   = threadIdx.x;
    if (blk < CI*CO*M1) {
        int ikp = blk;
        float wr = wp1_re[ikp], wi = wp1_im[ikp];
        float d = ty[1] - ty[0];
        float invnd = 1.0f / ((float)NY * d);
        float k = (o < NY/2) ? (float)o : (float)(o - NY);
        float lam = TWO_PI_F * k * invnd;
        float a = -wr, b = lam - wi;
        float inv = 1.0f / (a*a + b*b);
        g_A1[ikp*NY + o] = make_float2(a*inv, -b*inv);
        float t = ty[o];
        float e = expf(wr * t);
        float sn, cs; sincosf(wi * t, &sn, &cs);
        g_E1[ikp*NY + o] = make_float2(e*cs, e*sn);
    } else {
        int ikq = blk - CI*CO*M1;
        float wr = wp2_re[ikq], wi = wp2_im[ikq];
        float d = tx[1] - tx[0];
        float invnd = 1.0f / ((float)NX * d);
        float k = (o < NX/2) ? (float)o : (float)(o - NX);
        float lam = TWO_PI_F * k * invnd;
        float a = -wr, b = lam - wi;
        float inv = 1.0f / (a*a + b*b);
        g_A2[ikq*NX + o] = make_float2(a*inv, -b*inv);
        float t = tx[o];
        float e = expf(wr * t);
        float sn, cs; sincosf(wi * t, &sn, &cs);
        g_E2[ikq*NX + o] = make_float2(e*cs, e*sn);
    }
}

// ---------------- 128-pt radix-2 DIT ----------------------------------------
template<int INV>
__device__ __forceinline__ void fft64th(float2* s, int tt, const float2* tws) {
    #pragma unroll
    for (int stage = 1; stage <= 7; stage++) {
        __syncthreads();
        int half = 1 << (stage - 1);
        int p  = tt & (half - 1);
        int i0 = ((tt >> (stage - 1)) << stage) + p;
        int i1 = i0 + half;
        float2 w = tws[p << (7 - stage)];
        float wy = INV ? -w.y : w.y;
        float2 u = s[i0], v0 = s[i1];
        float2 v = make_float2(v0.x*w.x - v0.y*wy, v0.x*wy + v0.y*w.x);
        s[i0] = make_float2(u.x + v.x, u.y + v.y);
        s[i1] = make_float2(u.x - v.x, u.y - v.y);
    }
}

// forward FFT of real rows (launch 1)
__global__ void k_fft_rows_f(const float* __restrict__ x) {
    __shared__ float2 s[2][NX];
    __shared__ float2 tws[64];
    int t = threadIdx.x, r = t >> 6, tt = t & 63;
    make_tws(tws, t);
    size_t row = (size_t)blockIdx.x * 2 + r;
    const float* xr = x + row * NX;
    s[r][tt]      = make_float2(xr[__brev(tt)      >> 25], 0.f);
    s[r][tt + 64] = make_float2(xr[__brev(tt + 64) >> 25], 0.f);
    fft64th<0>(s[r], tt, tws);
    float2* o = g_tmp + row * NX;
    o[tt] = s[r][tt]; o[tt + 64] = s[r][tt + 64];
}

template<int INV>
__device__ __forceinline__ void fft_col(float2 (*tile)[17], int tg, int tx, const float2* tws) {
    #pragma unroll
    for (int stage = 1; stage <= 7; stage++) {
        __syncthreads();
        int half = 1 << (stage - 1);
        #pragma unroll
        for (int m = 0; m < 8; m++) {
            int j  = tg + 8 * m;
            int p  = j & (half - 1);
            int i0 = ((j >> (stage - 1)) << stage) + p;
            int i1 = i0 + half;
            float2 w = tws[p << (7 - stage)];
            float wy = INV ? -w.y : w.y;
            float2 u = tile[i0][tx], v0 = tile[i1][tx];
            float2 v = make_float2(v0.x*w.x - v0.y*wy, v0.x*wy + v0.y*w.x);
            tile[i0][tx] = make_float2(u.x + v.x, u.y + v.y);
            tile[i1][tx] = make_float2(u.x - v.x, u.y - v.y);
        }
    }
}

// forward columns (launch 2): g_tmp -> g_alpha
__global__ void k_fft_cols_f() {
    __shared__ float2 tile[NY][17];
    __shared__ float2 tws[64];
    int t = threadIdx.x;
    make_tws(tws, t);
    int blk = blockIdx.x;
    int xt = blk & 7, img = blk >> 3;
    int x0 = xt * 16;
    int tg = t >> 4, tx = t & 15;
    const float2* base = g_tmp + (size_t)img * NY * NX + x0;
    #pragma unroll
    for (int c = 0; c < 16; c++) {
        int y = c * 8 + tg;
        tile[__brev(y) >> 25][tx] = base[(size_t)y * NX + tx];
    }
    fft_col<0>(tile, tg, tx, tws);
    __syncthreads();
    float2* ob = g_alpha + (size_t)img * NY * NX + x0;
    #pragma unroll
    for (int c = 0; c < 16; c++) {
        int y = c * 8 + tg;
        ob[(size_t)y * NX + tx] = tile[y][tx];
    }
}

// ---------------- T2: o-tile 32, 3 blocks/SM, warp-broadcast B (launch 3) ---
// accP = sum a*b = {Σax·bx, Σay·by}  -> re = lo - hi
// accQ = sum swap(a)*b = {Σay·bx, Σax·by} -> im = lo + hi
// u = warp id (kq group of 5, broadcast LDS), v = lane (o row).
#define T2_OT 32
#define T2_KC 40
#define T2_PITCH 129
#define T2_SMEM ((T2_OT + T2_KC) * T2_PITCH * sizeof(float2))
extern __shared__ float2 t2sm[];
__global__ void __launch_bounds__(256, 3) k_T2() {
    float2* alphaS = t2sm;                      // [32 o][129 x]
    float2* a2S    = t2sm + T2_OT*T2_PITCH;     // [40 kq][129 x]
    const ull* alphaU = (const ull*)alphaS;
    const ull* a2U    = (const ull*)a2S;
    int blk = blockIdx.x;
    int oq = blk & 3;
    int bi = blk >> 2;
    int i  = bi & 31;
    int o0 = oq * T2_OT;
    int t  = threadIdx.x;
    const float2* A = g_alpha + (size_t)bi * NY * NX + (size_t)o0 * NX;
    #pragma unroll 4
    for (int l = t; l < T2_OT*128; l += 256) {
        int o = l >> 7, x = l & 127;
        alphaS[o*T2_PITCH + x] = A[(size_t)o * NX + x];
    }
    int u = t >> 5, v = t & 31;
    #pragma unroll 1
    for (int c = 0; c < 4; c++) {
        int kq0 = c * T2_KC;
        __syncthreads();
        for (int l = t; l < T2_KC*128; l += 256) {
            int r = l >> 7, x = l & 127;
            a2S[r*T2_PITCH + x] = g_A2[(size_t)(i*CO*M2 + kq0 + r) * NX + x];
        }
        __syncthreads();
        ull accP[5], accQ[5];
        #pragma unroll
        for (int j = 0; j < 5; j++) {
            accP[j] = pack2(0.f, 0.f);
            accQ[j] = pack2(0.f, 0.f);
        }
        #pragma unroll 4
        for (int x = 0; x < 128; x++) {
            ull bv[5];
            #pragma unroll
            for (int j = 0; j < 5; j++)
                bv[j] = a2U[(u*5 + j)*T2_PITCH + x];      // warp-broadcast
            ull av  = alphaU[v*T2_PITCH + x];
            ull asw = swap2(av);
            #pragma unroll
            for (int j = 0; j < 5; j++) {
                accP[j] = fma2(av,  bv[j], accP[j]);
                accQ[j] = fma2(asw, bv[j], accQ[j]);
            }
        }
        #pragma unroll
        for (int j = 0; j < 5; j++) {
            float2 p = unpack2(accP[j]);
            float2 q = unpack2(accQ[j]);
            g_T2[((size_t)bi * CO*M2 + kq0 + u*5 + j) * NY + o0 + v] =
                make_float2(p.x - p.y, q.x + q.y);
        }
    }
}

// ---------------- res2[b,k,p,q] = sum_i wr * sum_o A1[p,o]*T2[q,o] ---------
__global__ void k_res2(const float* __restrict__ wr_re, const float* __restrict__ wr_im) {
    int bk = blockIdx.x;
    int b = bk >> 5, k = bk & 31;
    int t = threadIdx.x;
    __shared__ float2 wrS[CI][M1*M2];
    for (int idx = t; idx < CI*M1*M2; idx += 128) {
        int i = idx / (M1*M2), pq = idx % (M1*M2);
        wrS[i][pq] = make_float2(wr_re[(i*CO + k)*M1*M2 + pq], wr_im[(i*CO + k)*M1*M2 + pq]);
    }
    __syncthreads();
    float2 acc[M1*M2];
    #pragma unroll
    for (int j = 0; j < M1*M2; j++) acc[j] = make_float2(0.f, 0.f);
    for (int i = 0; i < CI; i++) {
        float2 a1[M1], t2[M2];
        #pragma unroll
        for (int p = 0; p < M1; p++) a1[p] = g_A1[((i*CO + k)*M1 + p)*NY + t];
        #pragma unroll
        for (int q = 0; q < M2; q++) t2[q] = g_T2[(((size_t)(b*CI + i)*CO + k)*M2 + q)*NY + t];
        #pragma unroll
        for (int p = 0; p < M1; p++)
            #pragma unroll
            for (int q = 0; q < M2; q++) {
                float2 wa = cmul(wrS[i][p*M2 + q], a1[p]);
                acc[p*M2 + q] = cfma(wa, t2[q], acc[p*M2 + q]);
            }
    }
    #pragma unroll
    for (int j = 0; j < M1*M2; j++)
        #pragma unroll
        for (int off = 16; off; off >>= 1) {
            acc[j].x += __shfl_down_sync(0xffffffffu, acc[j].x, off);
            acc[j].y += __shfl_down_sync(0xffffffffu, acc[j].y, off);
        }
    __shared__ float2 red[4][M1*M2];
    int w = t >> 5, lane = t & 31;
    if (lane == 0) {
        #pragma unroll
        for (int j = 0; j < M1*M2; j++) red[w][j] = acc[j];
    }
    __syncthreads();
    if (t < M1*M2) {
        float2 s = red[0][t];
        #pragma unroll
        for (int w2 = 1; w2 < 4; w2++) { s.x += red[w2][t].x; s.y += red[w2][t].y; }
        g_res2[bk*M1*M2 + t] = s;
    }
}

// ---------------- G[b,c,k,q,z] = sum_p res2[b,c,p,q] * E1[c,k,p,z] ---------
__global__ void k_G() {
    int blk = blockIdx.x;
    int b = blk >> 10, c = (blk >> 5) & 31, k = blk & 31;
    int z = threadIdx.x;
    __shared__ float2 r2[M1*M2];
    if (z < M1*M2) r2[z] = g_res2[(b*CO + c)*M1*M2 + z];
    __syncthreads();
    float2 e1[M1];
    #pragma unroll
    for (int p = 0; p < M1; p++) e1[p] = g_E1[((c*CO + k)*M1 + p)*NY + z];
    #pragma unroll
    for (int q = 0; q < M2; q++) {
        float2 acc = make_float2(0.f, 0.f);
        #pragma unroll
        for (int p = 0; p < M1; p++) acc = cfma(r2[p*M2 + q], e1[p], acc);
        g_G[(((size_t)(b*CI + c)*CO + k)*M2 + q)*NY + z] = acc;
    }
}

// ---------------- Hsum full (streaming stores) ------------------------------
__global__ void k_hsum(const float* __restrict__ wr_re, const float* __restrict__ wr_im) {
    int ik = blockIdx.x;
    int t  = threadIdx.x;
    __shared__ float2 wrS[M1*M2];
    __shared__ float2 A1S[M1][NY];
    __shared__ float2 U[M2][NY];
    if (t < M1*M2) wrS[t] = make_float2(wr_re[ik*M1*M2 + t], wr_im[ik*M1*M2 + t]);
    #pragma unroll
    for (int p = 0; p < M1; p++) A1S[p][t] = g_A1[(ik*M1 + p)*NY + t];
    float2 a2[M2];
    #pragma unroll
    for (int q = 0; q < M2; q++) a2[q] = g_A2[(ik*M2 + q)*NX + t];
    __syncthreads();
    #pragma unroll
    for (int q = 0; q < M2; q++) {
        float2 acc = make_float2(0.f, 0.f);
        #pragma unroll
        for (int p = 0; p < M1; p++) acc = cfma(wrS[p*M2 + q], A1S[p][t], acc);
        U[q][t] = acc;
    }
    __syncthreads();
    float2* H = g_H + (size_t)ik * NY * NX;
    for (int o = 0; o < NY; o++) {
        float2 acc = make_float2(0.f, 0.f);
        #pragma unroll
        for (int q = 0; q < M2; q++) acc = cfma(U[q][o], a2[q], acc);
        __stcs(&H[o*NX + t], acc);
    }
}

// ---------------- res1 fused with inverse row FFT; prefetched ---------------
__global__ void __launch_bounds__(128, 3) k_res1f() {
    __shared__ float2 rows[32][129];
    __shared__ float2 tws[64];
    int o  = blockIdx.x & 127;
    int k0 = (blockIdx.x >> 7) * 4;
    int x  = threadIdx.x;
    make_tws(tws, x);
    ull acc[4][B];
    #pragma unroll
    for (int kk = 0; kk < 4; kk++)
        #pragma unroll
        for (int b = 0; b < B; b++) acc[kk][b] = pack2(0.f, 0.f);

    float2 hc[4], ac[8];
    #pragma unroll
    for (int kk = 0; kk < 4; kk++)
        hc[kk] = __ldcs(&g_H[((size_t)(0*CO + k0 + kk) * NY + o) * NX + x]);
    #pragma unroll
    for (int b = 0; b < B; b++)
        ac[b] = g_alpha[((size_t)(b*CI + 0) * NY + o) * NX + x];

    for (int i = 0; i < CI; i++) {
        float2 hn[4], an[8];
        if (i + 1 < CI) {
            #pragma unroll
            for (int kk = 0; kk < 4; kk++)
                hn[kk] = __ldcs(&g_H[((size_t)((i+1)*CO + k0 + kk) * NY + o) * NX + x]);
            #pragma unroll
            for (int b = 0; b < B; b++)
                an[b] = g_alpha[((size_t)(b*CI + i + 1) * NY + o) * NX + x];
        }
        ull hxx[4], hpm[4];
        #pragma unroll
        for (int kk = 0; kk < 4; kk++) {
            hxx[kk] = pack2(hc[kk].x,  hc[kk].x);
            hpm[kk] = pack2(-hc[kk].y, hc[kk].y);
        }
        #pragma unroll
        for (int b = 0; b < B; b++) {
            ull au = pack2(ac[b].x, ac[b].y);
            ull as = pack2(ac[b].y, ac[b].x);
            #pragma unroll
            for (int kk = 0; kk < 4; kk++) {
                acc[kk][b] = fma2(au, hxx[kk], acc[kk][b]);
                acc[kk][b] = fma2(as, hpm[kk], acc[kk][b]);
            }
        }
        if (i + 1 < CI) {
            #pragma unroll
            for (int kk = 0; kk < 4; kk++) hc[kk] = hn[kk];
            #pragma unroll
            for (int b = 0; b < B; b++) ac[b] = an[b];
        }
    }
    int xr = __brev(x) >> 25;
    #pragma unroll
    for (int kk = 0; kk < 4; kk++)
        #pragma unroll
        for (int b = 0; b < B; b++)
            rows[kk*8 + b][xr] = unpack2(acc[kk][b]);
    __syncthreads();
    #pragma unroll
    for (int stage = 1; stage <= 7; stage++) {
        int half = 1 << (stage - 1);
        #pragma unroll
        for (int m = 0; m < 16; m++) {
            int l = x + 128*m;
            int r = l >> 6, j = l & 63;
            int p = j & (half - 1);
            int i0 = ((j >> (stage - 1)) << stage) + p;
            int i1 = i0 + half;
            float2 w = tws[p << (7 - stage)];
            float2 u = rows[r][i0], v0 = rows[r][i1];
            float2 v = make_float2(v0.x*w.x + v0.y*w.y, -v0.x*w.y + v0.y*w.x);
            rows[r][i0] = make_float2(u.x + v.x, u.y + v.y);
            rows[r][i1] = make_float2(u.x - v.x, u.y - v.y);
        }
        __syncthreads();
    }
    #pragma unroll
    for (int kk = 0; kk < 4; kk++)
        #pragma unroll
        for (int b = 0; b < B; b++)
            g_tmp[(((size_t)(b*CO + k0 + kk)) * NY + o) * NX + x] = rows[kk*8 + b][x];
}

// inverse columns + real part + scale: g_tmp -> out
__global__ void k_ifft_cols_r(float* __restrict__ out) {
    __shared__ float2 tile[NY][17];
    __shared__ float2 tws[64];
    int t = threadIdx.x;
    make_tws(tws, t);
    int blk = blockIdx.x;
    int xt = blk & 7, img = blk >> 3;
    int x0 = xt * 16;
    int tg = t >> 4, tx = t & 15;
    const float2* base = g_tmp + (size_t)img * NY * NX + x0;
    #pragma unroll
    for (int c = 0; c < 16; c++) {
        int y = c * 8 + tg;
        tile[__brev(y) >> 25][tx] = base[(size_t)y * NX + tx];
    }
    fft_col<1>(tile, tg, tx, tws);
    __syncthreads();
    const float INV = 1.0f / (float)(NY * NX);
    float* ob = out + (size_t)img * NY * NX + x0;
    #pragma unroll
    for (int c = 0; c < 16; c++) {
        int y = c * 8 + tg;
        ob[(size_t)y * NX + tx] = tile[y][tx].x * INV;
    }
}

// ---------------- x2: out += Re( G[z,cq] * E2[cq,x] ) / (NY*NX) ------------
__global__ void __launch_bounds__(256, 2) k_x2(float* __restrict__ out) {
    __shared__ float2 Gs[16][66];
    __shared__ float2 Es[16][129];
    int blk = blockIdx.x;
    int zh  = blk & 1;
    int bk  = blk >> 1;
    int b = bk >> 5, k = bk & 31;
    int z0 = zh * 64;
    int t = threadIdx.x;
    int u = t >> 5, v = t & 31;
    ull acc[8][4];
    #pragma unroll
    for (int j = 0; j < 8; j++)
        #pragma unroll
        for (int m = 0; m < 4; m++) acc[j][m] = pack2(0.f, 0.f);
    for (int k0 = 0; k0 < CI*M2; k0 += 16) {
        __syncthreads();
        for (int l = t; l < 16*64; l += 256) {
            int r = l >> 6, zz = l & 63;
            int cq = k0 + r; int c = cq / M2, q = cq % M2;
            Gs[r][zz] = g_G[(((size_t)(b*CI + c)*CO + k)*M2 + q)*NY + z0 + zz];
        }
        for (int l = t; l < 16*128; l += 256) {
            int r = l >> 7, xx = l & 127;
            int cq = k0 + r; int c = cq / M2, q = cq % M2;
            Es[r][xx] = g_E2[((size_t)(c*CO + k)*M2 + q)*NX + xx];
        }
        __syncthreads();
        #pragma unroll
        for (int kk = 0; kk < 16; kk++) {
            ulonglong2 gp[4];
            const ulonglong2* gq = (const ulonglong2*)&Gs[kk][u*8];
            #pragma unroll
            for (int jp = 0; jp < 4; jp++) gp[jp] = gq[jp];
            #pragma unroll
            for (int m = 0; m < 4; m++) {
                ull e = *(const ull*)&Es[kk][v + 32*m];
                #pragma unroll
                for (int jp = 0; jp < 4; jp++) {
                    acc[2*jp  ][m] = fma2(gp[jp].x, e, acc[2*jp  ][m]);
                    acc[2*jp+1][m] = fma2(gp[jp].y, e, acc[2*jp+1][m]);
                }
            }
        }
    }
    const float INV = 1.0f / (float)(NY * NX);
    float* ob = out + (size_t)(b*CO + k) * NY * NX;
    #pragma unroll
    for (int j = 0; j < 8; j++) {
        int z = z0 + u*8 + j;
        #pragma unroll
        for (int m = 0; m < 4; m++) {
            float2 r = unpack2(acc[j][m]);
            ob[(size_t)z * NX + v + 32*m] += (r.x - r.y) * INV;
        }
    }
}

// ---------------------------------------------------------------------------
extern "C" void kernel_launch(void* const* d_in, const int* in_sizes, int n_in,
                              void* d_out, int out_size) {
    const float* x      = (const float*)d_in[0];
    const float* wp1_re = (const float*)d_in[1];
    const float* wp1_im = (const float*)d_in[2];
    const float* wp2_re = (const float*)d_in[3];
    const float* wp2_im = (const float*)d_in[4];
    const float* wr_re  = (const float*)d_in[5];
    const float* wr_im  = (const float*)d_in[6];
    const float* ty     = (const float*)d_in[7];
    const float* tx     = (const float*)d_in[8];
    float* out = (float*)d_out;

    cudaFuncSetAttribute(k_T2, cudaFuncAttributeMaxDynamicSharedMemorySize, (int)T2_SMEM);

    k_fac         <<<CI*CO*(M1+M2), 128>>>(wp1_re, wp1_im, wp2_re, wp2_im, ty, tx);  // 0
    k_fft_rows_f  <<<B*CI*NY/2, 128>>>(x);                                           // 1
    k_fft_cols_f  <<<B*CI*8, 128>>>();                                               // 2
    k_T2          <<<B*CI*4, 256, T2_SMEM>>>();                                      // 3 (profiled)
    k_res2        <<<B*CO, 128>>>(wr_re, wr_im);                                     // 4
    k_G           <<<B*CI*CO, 128>>>();                                              // 5
    k_hsum        <<<CI*CO, 128>>>(wr_re, wr_im);                                    // 6
    k_res1f       <<<8*NY, 128>>>();                                                 // 7
    k_ifft_cols_r <<<B*CO*8, 128>>>(out);                                            // 8
    k_x2          <<<B*CO*2, 256>>>(out);                                            // 9
}

// round 10
// speedup vs baseline: 1.1128x; 1.0982x over previous
#include <cuda_runtime.h>

#define B   8
#define CI  32
#define CO  32
#define NY  128
#define NX  128
#define M1  4
#define M2  5

#define TWO_PI_F 6.283185307179586476925f

typedef unsigned long long ull;

__device__ __forceinline__ float2 cmul(float2 a, float2 b) {
    return make_float2(a.x*b.x - a.y*b.y, a.x*b.y + a.y*b.x);
}
__device__ __forceinline__ float2 cfma(float2 a, float2 b, float2 c) {
    c.x = fmaf(a.x, b.x, fmaf(-a.y, b.y, c.x));
    c.y = fmaf(a.x, b.y, fmaf( a.y, b.x, c.y));
    return c;
}
__device__ __forceinline__ ull pack2(float lo, float hi) {
    ull r; asm("mov.b64 %0, {%1, %2};" : "=l"(r) : "f"(lo), "f"(hi)); return r;
}
__device__ __forceinline__ float2 unpack2(ull v) {
    float2 f; asm("mov.b64 {%0, %1}, %2;" : "=f"(f.x), "=f"(f.y) : "l"(v)); return f;
}
__device__ __forceinline__ ull fma2(ull a, ull b, ull c) {
    ull d; asm("fma.rn.f32x2 %0, %1, %2, %3;" : "=l"(d) : "l"(a), "l"(b), "l"(c)); return d;
}
__device__ __forceinline__ ull swap2(ull a) {
    float2 f = unpack2(a);
    return pack2(f.y, f.x);
}

// ---------------- scratch ---------------------------------------------------
__device__ float2 g_tmp  [B*CI*NY*NX];
__device__ float2 g_alpha[B*CI*NY*NX];
__device__ float2 g_A1   [CI*CO*M1*NY];
__device__ float2 g_A2   [CI*CO*M2*NX];
__device__ float2 g_E1   [CI*CO*M1*NY];
__device__ float2 g_E2   [CI*CO*M2*NX];
__device__ float2 g_H    [CI*CO*NY*NX];
__device__ float2 g_T2   [B*CI*CO*M2*NY];
__device__ float2 g_res2 [B*CO*M1*M2];

__device__ __forceinline__ void make_tws(float2* tws, int t) {
    if (t < 64) {
        float sn, cs;
        sincospif(-(float)t / 64.f, &sn, &cs);
        tws[t] = make_float2(cs, sn);
    }
}

// ---------------- Hsum with inline A1/A2 (launch 0) --------------------------
__global__ void k_hsum(const float* __restrict__ wp1_re, const float* __restrict__ wp1_im,
                       const float* __restrict__ wp2_re, const float* __restrict__ wp2_im,
                       const float* __restrict__ ty, const float* __restrict__ tx,
                       const float* __restrict__ wr_re, const float* __restrict__ wr_im) {
    int ik = blockIdx.x;
    int t  = threadIdx.x;
    __shared__ float2 wrS[M1*M2];
    __shared__ float2 A1S[M1][NY];
    __shared__ float2 U[M2][NY];
    if (t < M1*M2) wrS[t] = make_float2(wr_re[ik*M1*M2 + t], wr_im[ik*M1*M2 + t]);
    float kf = (t < NY/2) ? (float)t : (float)(t - NY);
    {
        float d = ty[1] - ty[0];
        float invnd = 1.0f / ((float)NY * d);
        float lam = TWO_PI_F * kf * invnd;
        #pragma unroll
        for (int p = 0; p < M1; p++) {
            float wr = wp1_re[ik*M1 + p], wi = wp1_im[ik*M1 + p];
            float a = -wr, b = lam - wi;
            float inv = 1.0f / (a*a + b*b);
            A1S[p][t] = make_float2(a*inv, -b*inv);
        }
    }
    float2 a2[M2];
    {
        float d = tx[1] - tx[0];
        float invnd = 1.0f / ((float)NX * d);
        float lam = TWO_PI_F * kf * invnd;
        #pragma unroll
        for (int q = 0; q < M2; q++) {
            float wr = wp2_re[ik*M2 + q], wi = wp2_im[ik*M2 + q];
            float a = -wr, b = lam - wi;
            float inv = 1.0f / (a*a + b*b);
            a2[q] = make_float2(a*inv, -b*inv);
        }
    }
    __syncthreads();
    #pragma unroll
    for (int q = 0; q < M2; q++) {
        float2 acc = make_float2(0.f, 0.f);
        #pragma unroll
        for (int p = 0; p < M1; p++) acc = cfma(wrS[p*M2 + q], A1S[p][t], acc);
        U[q][t] = acc;
    }
    __syncthreads();
    float2* H = g_H + (size_t)ik * NY * NX;
    for (int o = 0; o < NY; o++) {
        float2 acc = make_float2(0.f, 0.f);
        #pragma unroll
        for (int q = 0; q < M2; q++) acc = cfma(U[q][o], a2[q], acc);
        __stcs(&H[o*NX + t], acc);
    }
}

// ---------------- 128-pt radix-2 DIT ----------------------------------------
template<int INV>
__device__ __forceinline__ void fft64th(float2* s, int tt, const float2* tws) {
    #pragma unroll
    for (int stage = 1; stage <= 7; stage++) {
        __syncthreads();
        int half = 1 << (stage - 1);
        int p  = tt & (half - 1);
        int i0 = ((tt >> (stage - 1)) << stage) + p;
        int i1 = i0 + half;
        float2 w = tws[p << (7 - stage)];
        float wy = INV ? -w.y : w.y;
        float2 u = s[i0], v0 = s[i1];
        float2 v = make_float2(v0.x*w.x - v0.y*wy, v0.x*wy + v0.y*w.x);
        s[i0] = make_float2(u.x + v.x, u.y + v.y);
        s[i1] = make_float2(u.x - v.x, u.y - v.y);
    }
}

// forward FFT of real rows (launch 1)
__global__ void k_fft_rows_f(const float* __restrict__ x) {
    __shared__ float2 s[2][NX];
    __shared__ float2 tws[64];
    int t = threadIdx.x, r = t >> 6, tt = t & 63;
    make_tws(tws, t);
    size_t row = (size_t)blockIdx.x * 2 + r;
    const float* xr = x + row * NX;
    s[r][tt]      = make_float2(xr[__brev(tt)      >> 25], 0.f);
    s[r][tt + 64] = make_float2(xr[__brev(tt + 64) >> 25], 0.f);
    fft64th<0>(s[r], tt, tws);
    float2* o = g_tmp + row * NX;
    o[tt] = s[r][tt]; o[tt + 64] = s[r][tt + 64];
}

template<int INV>
__device__ __forceinline__ void fft_col(float2 (*tile)[17], int tg, int tx, const float2* tws) {
    #pragma unroll
    for (int stage = 1; stage <= 7; stage++) {
        __syncthreads();
        int half = 1 << (stage - 1);
        #pragma unroll
        for (int m = 0; m < 8; m++) {
            int j  = tg + 8 * m;
            int p  = j & (half - 1);
            int i0 = ((j >> (stage - 1)) << stage) + p;
            int i1 = i0 + half;
            float2 w = tws[p << (7 - stage)];
            float wy = INV ? -w.y : w.y;
            float2 u = tile[i0][tx], v0 = tile[i1][tx];
            float2 v = make_float2(v0.x*w.x - v0.y*wy, v0.x*wy + v0.y*w.x);
            tile[i0][tx] = make_float2(u.x + v.x, u.y + v.y);
            tile[i1][tx] = make_float2(u.x - v.x, u.y - v.y);
        }
    }
}

// forward columns (launch 2): g_tmp -> g_alpha
__global__ void k_fft_cols_f() {
    __shared__ float2 tile[NY][17];
    __shared__ float2 tws[64];
    int t = threadIdx.x;
    make_tws(tws, t);
    int blk = blockIdx.x;
    int xt = blk & 7, img = blk >> 3;
    int x0 = xt * 16;
    int tg = t >> 4, tx = t & 15;
    const float2* base = g_tmp + (size_t)img * NY * NX + x0;
    #pragma unroll
    for (int c = 0; c < 16; c++) {
        int y = c * 8 + tg;
        tile[__brev(y) >> 25][tx] = base[(size_t)y * NX + tx];
    }
    fft_col<0>(tile, tg, tx, tws);
    __syncthreads();
    float2* ob = g_alpha + (size_t)img * NY * NX + x0;
    #pragma unroll
    for (int c = 0; c < 16; c++) {
        int y = c * 8 + tg;
        ob[(size_t)y * NX + tx] = tile[y][tx];
    }
}

// ---------------- res1 fused with inverse row FFT (launch 3 -> profiled) -----
__global__ void __launch_bounds__(128, 3) k_res1f() {
    __shared__ float2 rows[32][129];
    __shared__ float2 tws[64];
    int o  = blockIdx.x & 127;
    int k0 = (blockIdx.x >> 7) * 4;
    int x  = threadIdx.x;
    make_tws(tws, x);
    const ull* alphaU = (const ull*)g_alpha;
    ull acc[4][B];
    #pragma unroll
    for (int kk = 0; kk < 4; kk++)
        #pragma unroll
        for (int b = 0; b < B; b++) acc[kk][b] = pack2(0.f, 0.f);

    float2 hc[4]; ull ac[8];
    #pragma unroll
    for (int kk = 0; kk < 4; kk++)
        hc[kk] = __ldcs(&g_H[((size_t)(0*CO + k0 + kk) * NY + o) * NX + x]);
    #pragma unroll
    for (int b = 0; b < B; b++)
        ac[b] = alphaU[((size_t)(b*CI + 0) * NY + o) * NX + x];

    for (int i = 0; i < CI; i++) {
        float2 hn[4]; ull an[8];
        if (i + 1 < CI) {
            #pragma unroll
            for (int kk = 0; kk < 4; kk++)
                hn[kk] = __ldcs(&g_H[((size_t)((i+1)*CO + k0 + kk) * NY + o) * NX + x]);
            #pragma unroll
            for (int b = 0; b < B; b++)
                an[b] = alphaU[((size_t)(b*CI + i + 1) * NY + o) * NX + x];
        }
        ull hxx[4], hpm[4];
        #pragma unroll
        for (int kk = 0; kk < 4; kk++) {
            hxx[kk] = pack2(hc[kk].x,  hc[kk].x);
            hpm[kk] = pack2(-hc[kk].y, hc[kk].y);
        }
        #pragma unroll
        for (int b = 0; b < B; b++) {
            ull au = ac[b];
            ull as = swap2(au);
            #pragma unroll
            for (int kk = 0; kk < 4; kk++) {
                acc[kk][b] = fma2(au, hxx[kk], acc[kk][b]);
                acc[kk][b] = fma2(as, hpm[kk], acc[kk][b]);
            }
        }
        if (i + 1 < CI) {
            #pragma unroll
            for (int kk = 0; kk < 4; kk++) hc[kk] = hn[kk];
            #pragma unroll
            for (int b = 0; b < B; b++) ac[b] = an[b];
        }
    }
    int xr = __brev(x) >> 25;
    #pragma unroll
    for (int kk = 0; kk < 4; kk++)
        #pragma unroll
        for (int b = 0; b < B; b++)
            rows[kk*8 + b][xr] = unpack2(acc[kk][b]);
    __syncthreads();
    #pragma unroll
    for (int stage = 1; stage <= 7; stage++) {
        int half = 1 << (stage - 1);
        #pragma unroll
        for (int m = 0; m < 16; m++) {
            int l = x + 128*m;
            int r = l >> 6, j = l & 63;
            int p = j & (half - 1);
            int i0 = ((j >> (stage - 1)) << stage) + p;
            int i1 = i0 + half;
            float2 w = tws[p << (7 - stage)];
            float2 u = rows[r][i0], v0 = rows[r][i1];
            float2 v = make_float2(v0.x*w.x + v0.y*w.y, -v0.x*w.y + v0.y*w.x);
            rows[r][i0] = make_float2(u.x + v.x, u.y + v.y);
            rows[r][i1] = make_float2(u.x - v.x, u.y - v.y);
        }
        __syncthreads();
    }
    #pragma unroll
    for (int kk = 0; kk < 4; kk++)
        #pragma unroll
        for (int b = 0; b < B; b++)
            g_tmp[(((size_t)(b*CO + k0 + kk)) * NY + o) * NX + x] = rows[kk*8 + b][x];
}

// ---------------- pole factors E1/E2 + A1/A2 (launch 4) ----------------------
__global__ void k_fac(const float* __restrict__ wp1_re, const float* __restrict__ wp1_im,
                      const float* __restrict__ wp2_re, const float* __restrict__ wp2_im,
                      const float* __restrict__ ty, const float* __restrict__ tx) {
    int blk = blockIdx.x;
    int o   = threadIdx.x;
    if (blk < CI*CO*M1) {
        int ikp = blk;
        float wr = wp1_re[ikp], wi = wp1_im[ikp];
        float d = ty[1] - ty[0];
        float invnd = 1.0f / ((float)NY * d);
        float k = (o < NY/2) ? (float)o : (float)(o - NY);
        float lam = TWO_PI_F * k * invnd;
        float a = -wr, b = lam - wi;
        float inv = 1.0f / (a*a + b*b);
        g_A1[ikp*NY + o] = make_float2(a*inv, -b*inv);
        float t = ty[o];
        float e = expf(wr * t);
        float sn, cs; sincosf(wi * t, &sn, &cs);
        g_E1[ikp*NY + o] = make_float2(e*cs, e*sn);
    } else {
        int ikq = blk - CI*CO*M1;
        float wr = wp2_re[ikq], wi = wp2_im[ikq];
        float d = tx[1] - tx[0];
        float invnd = 1.0f / ((float)NX * d);
        float k = (o < NX/2) ? (float)o : (float)(o - NX);
        float lam = TWO_PI_F * k * invnd;
        float a = -wr, b = lam - wi;
        float inv = 1.0f / (a*a + b*b);
        g_A2[ikq*NX + o] = make_float2(a*inv, -b*inv);
        float t = tx[o];
        float e = expf(wr * t);
        float sn, cs; sincosf(wi * t, &sn, &cs);
        g_E2[ikq*NX + o] = make_float2(e*cs, e*sn);
    }
}

// ---------------- T2 (launch 5): o-tile 32, warp-broadcast B -----------------
#define T2_OT 32
#define T2_KC 40
#define T2_PITCH 129
#define T2_SMEM ((T2_OT + T2_KC) * T2_PITCH * sizeof(float2))
extern __shared__ float2 dynsm[];
__global__ void __launch_bounds__(256, 3) k_T2() {
    float2* alphaS = dynsm;
    float2* a2S    = dynsm + T2_OT*T2_PITCH;
    const ull* alphaU = (const ull*)alphaS;
    const ull* a2U    = (const ull*)a2S;
    int blk = blockIdx.x;
    int oq = blk & 3;
    int bi = blk >> 2;
    int i  = bi & 31;
    int o0 = oq * T2_OT;
    int t  = threadIdx.x;
    const float2* A = g_alpha + (size_t)bi * NY * NX + (size_t)o0 * NX;
    #pragma unroll 4
    for (int l = t; l < T2_OT*128; l += 256) {
        int o = l >> 7, x = l & 127;
        alphaS[o*T2_PITCH + x] = A[(size_t)o * NX + x];
    }
    int u = t >> 5, v = t & 31;
    #pragma unroll 1
    for (int c = 0; c < 4; c++) {
        int kq0 = c * T2_KC;
        __syncthreads();
        for (int l = t; l < T2_KC*128; l += 256) {
            int r = l >> 7, x = l & 127;
            a2S[r*T2_PITCH + x] = g_A2[(size_t)(i*CO*M2 + kq0 + r) * NX + x];
        }
        __syncthreads();
        ull accP[5], accQ[5];
        #pragma unroll
        for (int j = 0; j < 5; j++) {
            accP[j] = pack2(0.f, 0.f);
            accQ[j] = pack2(0.f, 0.f);
        }
        #pragma unroll 4
        for (int x = 0; x < 128; x++) {
            ull bv[5];
            #pragma unroll
            for (int j = 0; j < 5; j++)
                bv[j] = a2U[(u*5 + j)*T2_PITCH + x];
            ull av  = alphaU[v*T2_PITCH + x];
            ull asw = swap2(av);
            #pragma unroll
            for (int j = 0; j < 5; j++) {
                accP[j] = fma2(av,  bv[j], accP[j]);
                accQ[j] = fma2(asw, bv[j], accQ[j]);
            }
        }
        #pragma unroll
        for (int j = 0; j < 5; j++) {
            float2 p = unpack2(accP[j]);
            float2 q = unpack2(accQ[j]);
            g_T2[((size_t)bi * CO*M2 + kq0 + u*5 + j) * NY + o0 + v] =
                make_float2(p.x - p.y, q.x + q.y);
        }
    }
}

// ---------------- res2 (launch 6) -------------------------------------------
__global__ void k_res2(const float* __restrict__ wr_re, const float* __restrict__ wr_im) {
    int bk = blockIdx.x;
    int b = bk >> 5, k = bk & 31;
    int t = threadIdx.x;
    __shared__ float2 wrS[CI][M1*M2];
    for (int idx = t; idx < CI*M1*M2; idx += 128) {
        int i = idx / (M1*M2), pq = idx % (M1*M2);
        wrS[i][pq] = make_float2(wr_re[(i*CO + k)*M1*M2 + pq], wr_im[(i*CO + k)*M1*M2 + pq]);
    }
    __syncthreads();
    float2 acc[M1*M2];
    #pragma unroll
    for (int j = 0; j < M1*M2; j++) acc[j] = make_float2(0.f, 0.f);
    for (int i = 0; i < CI; i++) {
        float2 a1[M1], t2[M2];
        #pragma unroll
        for (int p = 0; p < M1; p++) a1[p] = g_A1[((i*CO + k)*M1 + p)*NY + t];
        #pragma unroll
        for (int q = 0; q < M2; q++) t2[q] = g_T2[(((size_t)(b*CI + i)*CO + k)*M2 + q)*NY + t];
        #pragma unroll
        for (int p = 0; p < M1; p++)
            #pragma unroll
            for (int q = 0; q < M2; q++) {
                float2 wa = cmul(wrS[i][p*M2 + q], a1[p]);
                acc[p*M2 + q] = cfma(wa, t2[q], acc[p*M2 + q]);
            }
    }
    #pragma unroll
    for (int j = 0; j < M1*M2; j++)
        #pragma unroll
        for (int off = 16; off; off >>= 1) {
            acc[j].x += __shfl_down_sync(0xffffffffu, acc[j].x, off);
            acc[j].y += __shfl_down_sync(0xffffffffu, acc[j].y, off);
        }
    __shared__ float2 red[4][M1*M2];
    int w = t >> 5, lane = t & 31;
    if (lane == 0) {
        #pragma unroll
        for (int j = 0; j < M1*M2; j++) red[w][j] = acc[j];
    }
    __syncthreads();
    if (t < M1*M2) {
        float2 s = red[0][t];
        #pragma unroll
        for (int w2 = 1; w2 < 4; w2++) { s.x += red[w2][t].x; s.y += red[w2][t].y; }
        g_res2[bk*M1*M2 + t] = s;
    }
}

// ---------------- inverse columns (launch 7) ---------------------------------
__global__ void k_ifft_cols_r(float* __restrict__ out) {
    __shared__ float2 tile[NY][17];
    __shared__ float2 tws[64];
    int t = threadIdx.x;
    make_tws(tws, t);
    int blk = blockIdx.x;
    int xt = blk & 7, img = blk >> 3;
    int x0 = xt * 16;
    int tg = t >> 4, tx = t & 15;
    const float2* base = g_tmp + (size_t)img * NY * NX + x0;
    #pragma unroll
    for (int c = 0; c < 16; c++) {
        int y = c * 8 + tg;
        tile[__brev(y) >> 25][tx] = base[(size_t)y * NX + tx];
    }
    fft_col<1>(tile, tg, tx, tws);
    __syncthreads();
    const float INV = 1.0f / (float)(NY * NX);
    float* ob = out + (size_t)img * NY * NX + x0;
    #pragma unroll
    for (int c = 0; c < 16; c++) {
        int y = c * 8 + tg;
        ob[(size_t)y * NX + tx] = tile[y][tx].x * INV;
    }
}

// ---------------- x2 with fused G (launch 8) ---------------------------------
// Gs tile computed in-block: Gs[r][zz] = sum_p res2[b,c,p,q] * E1[c,k,p,z0+zz]
#define X2_E1   (128*64)
#define X2_R2   (CI*M1*M2)
#define X2_GS   (16*66)
#define X2_ES   (16*129)
#define X2_SMEM ((X2_E1 + X2_R2 + X2_GS + X2_ES) * sizeof(float2))
__global__ void __launch_bounds__(256) k_x2(float* __restrict__ out) {
    float2* e1S = dynsm;                 // [c*4+p][64 zz]
    float2* r2S = e1S + X2_E1;           // [c][p*5+q]
    float2* Gs  = r2S + X2_R2;           // [16][66]
    float2* Es  = Gs + X2_GS;            // [16][129]
    int blk = blockIdx.x;
    int zh  = blk & 1;
    int bk  = blk >> 1;
    int b = bk >> 5, k = bk & 31;
    int z0 = zh * 64;
    int t = threadIdx.x;
    int u = t >> 5, v = t & 31;
    // load E1 slice (c,p,z-half) and res2 slice
    for (int l = t; l < X2_E1; l += 256) {
        int cp = l >> 6, zz = l & 63;
        e1S[l] = g_E1[(((cp >> 2)*CO + k)*M1 + (cp & 3))*NY + z0 + zz];
    }
    for (int l = t; l < X2_R2; l += 256)
        r2S[l] = g_res2[(b*CO + (l/20))*20 + (l%20)];
    ull acc[8][4];
    #pragma unroll
    for (int j = 0; j < 8; j++)
        #pragma unroll
        for (int m = 0; m < 4; m++) acc[j][m] = pack2(0.f, 0.f);
    for (int k0 = 0; k0 < CI*M2; k0 += 16) {
        __syncthreads();
        for (int l = t; l < 16*64; l += 256) {
            int r = l >> 6, zz = l & 63;
            int cq = k0 + r; int c = cq / M2, q = cq % M2;
            float2 g = make_float2(0.f, 0.f);
            #pragma unroll
            for (int p = 0; p < M1; p++)
                g = cfma(r2S[c*20 + p*M2 + q], e1S[(c*4 + p)*64 + zz], g);
            Gs[r*66 + zz] = g;
        }
        for (int l = t; l < 16*128; l += 256) {
            int r = l >> 7, xx = l & 127;
            int cq = k0 + r; int c = cq / M2, q = cq % M2;
            Es[r*129 + xx] = g_E2[((size_t)(c*CO + k)*M2 + q)*NX + xx];
        }
        __syncthreads();
        #pragma unroll
        for (int kk = 0; kk < 16; kk++) {
            ulonglong2 gp[4];
            const ulonglong2* gq = (const ulonglong2*)&Gs[kk*66 + u*8];
            #pragma unroll
            for (int jp = 0; jp < 4; jp++) gp[jp] = gq[jp];
            #pragma unroll
            for (int m = 0; m < 4; m++) {
                ull e = *(const ull*)&Es[kk*129 + v + 32*m];
                #pragma unroll
                for (int jp = 0; jp < 4; jp++) {
                    acc[2*jp  ][m] = fma2(gp[jp].x, e, acc[2*jp  ][m]);
                    acc[2*jp+1][m] = fma2(gp[jp].y, e, acc[2*jp+1][m]);
                }
            }
        }
    }
    const float INV = 1.0f / (float)(NY * NX);
    float* ob = out + (size_t)(b*CO + k) * NY * NX;
    #pragma unroll
    for (int j = 0; j < 8; j++) {
        int z = z0 + u*8 + j;
        #pragma unroll
        for (int m = 0; m < 4; m++) {
            float2 r = unpack2(acc[j][m]);
            ob[(size_t)z * NX + v + 32*m] += (r.x - r.y) * INV;
        }
    }
}

// ---------------------------------------------------------------------------
extern "C" void kernel_launch(void* const* d_in, const int* in_sizes, int n_in,
                              void* d_out, int out_size) {
    const float* x      = (const float*)d_in[0];
    const float* wp1_re = (const float*)d_in[1];
    const float* wp1_im = (const float*)d_in[2];
    const float* wp2_re = (const float*)d_in[3];
    const float* wp2_im = (const float*)d_in[4];
    const float* wr_re  = (const float*)d_in[5];
    const float* wr_im  = (const float*)d_in[6];
    const float* ty     = (const float*)d_in[7];
    const float* tx     = (const float*)d_in[8];
    float* out = (float*)d_out;

    cudaFuncSetAttribute(k_T2, cudaFuncAttributeMaxDynamicSharedMemorySize, (int)T2_SMEM);
    cudaFuncSetAttribute(k_x2, cudaFuncAttributeMaxDynamicSharedMemorySize, (int)X2_SMEM);

    k_hsum        <<<CI*CO, 128>>>(wp1_re, wp1_im, wp2_re, wp2_im, ty, tx, wr_re, wr_im); // 0
    k_fft_rows_f  <<<B*CI*NY/2, 128>>>(x);                                                // 1
    k_fft_cols_f  <<<B*CI*8, 128>>>();                                                    // 2
    k_res1f       <<<8*NY, 128>>>();                                                      // 3 (profiled)
    k_fac         <<<CI*CO*(M1+M2), 128>>>(wp1_re, wp1_im, wp2_re, wp2_im, ty, tx);       // 4
    k_T2          <<<B*CI*4, 256, T2_SMEM>>>();                                           // 5
    k_res2        <<<B*CO, 128>>>(wr_re, wr_im);                                          // 6
    k_ifft_cols_r <<<B*CO*8, 128>>>(out);                                                 // 7
    k_x2          <<<B*CO*2, 256, X2_SMEM>>>(out);                                        // 8
}

// round 11
// speedup vs baseline: 1.1866x; 1.0664x over previous
#include <cuda_runtime.h>

#define B   8
#define CI  32
#define CO  32
#define NY  128
#define NX  128
#define M1  4
#define M2  5

#define TWO_PI_F 6.283185307179586476925f

typedef unsigned long long ull;

__device__ __forceinline__ float2 cmul(float2 a, float2 b) {
    return make_float2(a.x*b.x - a.y*b.y, a.x*b.y + a.y*b.x);
}
__device__ __forceinline__ float2 cfma(float2 a, float2 b, float2 c) {
    c.x = fmaf(a.x, b.x, fmaf(-a.y, b.y, c.x));
    c.y = fmaf(a.x, b.y, fmaf( a.y, b.x, c.y));
    return c;
}
__device__ __forceinline__ ull pack2(float lo, float hi) {
    ull r; asm("mov.b64 %0, {%1, %2};" : "=l"(r) : "f"(lo), "f"(hi)); return r;
}
__device__ __forceinline__ float2 unpack2(ull v) {
    float2 f; asm("mov.b64 {%0, %1}, %2;" : "=f"(f.x), "=f"(f.y) : "l"(v)); return f;
}
__device__ __forceinline__ ull fma2(ull a, ull b, ull c) {
    ull d; asm("fma.rn.f32x2 %0, %1, %2, %3;" : "=l"(d) : "l"(a), "l"(b), "l"(c)); return d;
}
__device__ __forceinline__ ull swap2(ull a) {
    float2 f = unpack2(a);
    return pack2(f.y, f.x);
}

// ---------------- scratch ---------------------------------------------------
__device__ float2 g_tmp  [B*CI*NY*NX];
__device__ float2 g_alpha[B*CI*NY*NX];
__device__ float2 g_A1   [CI*CO*M1*NY];
__device__ float2 g_A2   [CI*CO*M2*NX];
__device__ float2 g_E1   [CI*CO*M1*NY];
__device__ float2 g_E2   [CI*CO*M2*NX];
__device__ float2 g_H    [CI*CO*NY*NX];
__device__ float2 g_T2   [B*CI*CO*M2*NY];
__device__ float2 g_res2 [B*CO*M1*M2];

__device__ __forceinline__ void make_tws(float2* tws, int t) {
    if (t < 64) {
        float sn, cs;
        sincospif(-(float)t / 64.f, &sn, &cs);
        tws[t] = make_float2(cs, sn);
    }
}

// ---------------- Hsum with inline A1/A2 (launch 0) --------------------------
__global__ void k_hsum(const float* __restrict__ wp1_re, const float* __restrict__ wp1_im,
                       const float* __restrict__ wp2_re, const float* __restrict__ wp2_im,
                       const float* __restrict__ ty, const float* __restrict__ tx,
                       const float* __restrict__ wr_re, const float* __restrict__ wr_im) {
    int ik = blockIdx.x;
    int t  = threadIdx.x;
    __shared__ float2 wrS[M1*M2];
    __shared__ float2 A1S[M1][NY];
    __shared__ float2 U[M2][NY];
    if (t < M1*M2) wrS[t] = make_float2(wr_re[ik*M1*M2 + t], wr_im[ik*M1*M2 + t]);
    float kf = (t < NY/2) ? (float)t : (float)(t - NY);
    {
        float d = ty[1] - ty[0];
        float invnd = 1.0f / ((float)NY * d);
        float lam = TWO_PI_F * kf * invnd;
        #pragma unroll
        for (int p = 0; p < M1; p++) {
            float wr = wp1_re[ik*M1 + p], wi = wp1_im[ik*M1 + p];
            float a = -wr, b = lam - wi;
            float inv = 1.0f / (a*a + b*b);
            A1S[p][t] = make_float2(a*inv, -b*inv);
        }
    }
    float2 a2[M2];
    {
        float d = tx[1] - tx[0];
        float invnd = 1.0f / ((float)NX * d);
        float lam = TWO_PI_F * kf * invnd;
        #pragma unroll
        for (int q = 0; q < M2; q++) {
            float wr = wp2_re[ik*M2 + q], wi = wp2_im[ik*M2 + q];
            float a = -wr, b = lam - wi;
            float inv = 1.0f / (a*a + b*b);
            a2[q] = make_float2(a*inv, -b*inv);
        }
    }
    __syncthreads();
    #pragma unroll
    for (int q = 0; q < M2; q++) {
        float2 acc = make_float2(0.f, 0.f);
        #pragma unroll
        for (int p = 0; p < M1; p++) acc = cfma(wrS[p*M2 + q], A1S[p][t], acc);
        U[q][t] = acc;
    }
    __syncthreads();
    float2* H = g_H + (size_t)ik * NY * NX;
    for (int o = 0; o < NY; o++) {
        float2 acc = make_float2(0.f, 0.f);
        #pragma unroll
        for (int q = 0; q < M2; q++) acc = cfma(U[q][o], a2[q], acc);
        __stcs(&H[o*NX + t], acc);
    }
}

// ---------------- 128-pt radix-2 DIT ----------------------------------------
template<int INV>
__device__ __forceinline__ void fft64th(float2* s, int tt, const float2* tws) {
    #pragma unroll
    for (int stage = 1; stage <= 7; stage++) {
        __syncthreads();
        int half = 1 << (stage - 1);
        int p  = tt & (half - 1);
        int i0 = ((tt >> (stage - 1)) << stage) + p;
        int i1 = i0 + half;
        float2 w = tws[p << (7 - stage)];
        float wy = INV ? -w.y : w.y;
        float2 u = s[i0], v0 = s[i1];
        float2 v = make_float2(v0.x*w.x - v0.y*wy, v0.x*wy + v0.y*w.x);
        s[i0] = make_float2(u.x + v.x, u.y + v.y);
        s[i1] = make_float2(u.x - v.x, u.y - v.y);
    }
}

// forward FFT of real rows (launch 1)
__global__ void k_fft_rows_f(const float* __restrict__ x) {
    __shared__ float2 s[2][NX];
    __shared__ float2 tws[64];
    int t = threadIdx.x, r = t >> 6, tt = t & 63;
    make_tws(tws, t);
    size_t row = (size_t)blockIdx.x * 2 + r;
    const float* xr = x + row * NX;
    s[r][tt]      = make_float2(xr[__brev(tt)      >> 25], 0.f);
    s[r][tt + 64] = make_float2(xr[__brev(tt + 64) >> 25], 0.f);
    fft64th<0>(s[r], tt, tws);
    float2* o = g_tmp + row * NX;
    o[tt] = s[r][tt]; o[tt + 64] = s[r][tt + 64];
}

template<int INV>
__device__ __forceinline__ void fft_col(float2 (*tile)[17], int tg, int tx, const float2* tws) {
    #pragma unroll
    for (int stage = 1; stage <= 7; stage++) {
        __syncthreads();
        int half = 1 << (stage - 1);
        #pragma unroll
        for (int m = 0; m < 8; m++) {
            int j  = tg + 8 * m;
            int p  = j & (half - 1);
            int i0 = ((j >> (stage - 1)) << stage) + p;
            int i1 = i0 + half;
            float2 w = tws[p << (7 - stage)];
            float wy = INV ? -w.y : w.y;
            float2 u = tile[i0][tx], v0 = tile[i1][tx];
            float2 v = make_float2(v0.x*w.x - v0.y*wy, v0.x*wy + v0.y*w.x);
            tile[i0][tx] = make_float2(u.x + v.x, u.y + v.y);
            tile[i1][tx] = make_float2(u.x - v.x, u.y - v.y);
        }
    }
}

// forward columns (launch 2): g_tmp -> g_alpha
__global__ void k_fft_cols_f() {
    __shared__ float2 tile[NY][17];
    __shared__ float2 tws[64];
    int t = threadIdx.x;
    make_tws(tws, t);
    int blk = blockIdx.x;
    int xt = blk & 7, img = blk >> 3;
    int x0 = xt * 16;
    int tg = t >> 4, tx = t & 15;
    const float2* base = g_tmp + (size_t)img * NY * NX + x0;
    #pragma unroll
    for (int c = 0; c < 16; c++) {
        int y = c * 8 + tg;
        tile[__brev(y) >> 25][tx] = base[(size_t)y * NX + tx];
    }
    fft_col<0>(tile, tg, tx, tws);
    __syncthreads();
    float2* ob = g_alpha + (size_t)img * NY * NX + x0;
    #pragma unroll
    for (int c = 0; c < 16; c++) {
        int y = c * 8 + tg;
        ob[(size_t)y * NX + tx] = tile[y][tx];
    }
}

// ---------------- res1 + inverse row FFT, k-tile 2, high-occ (launch 3) ------
__global__ void __launch_bounds__(128, 5) k_res1f() {
    __shared__ float2 rows[16][129];
    __shared__ float2 tws[64];
    int o  = blockIdx.x & 127;
    int k0 = (blockIdx.x >> 7) * 2;
    int x  = threadIdx.x;
    make_tws(tws, x);
    const ull* alphaU = (const ull*)g_alpha;
    ull acc[2][B];
    #pragma unroll
    for (int kk = 0; kk < 2; kk++)
        #pragma unroll
        for (int b = 0; b < B; b++) acc[kk][b] = pack2(0.f, 0.f);

    for (int i = 0; i < CI; i++) {
        float2 hc[2];
        #pragma unroll
        for (int kk = 0; kk < 2; kk++)
            hc[kk] = __ldcs(&g_H[((size_t)(i*CO + k0 + kk) * NY + o) * NX + x]);
        ull ac[8];
        #pragma unroll
        for (int b = 0; b < B; b++)
            ac[b] = alphaU[((size_t)(b*CI + i) * NY + o) * NX + x];
        ull hxx[2], hpm[2];
        #pragma unroll
        for (int kk = 0; kk < 2; kk++) {
            hxx[kk] = pack2(hc[kk].x,  hc[kk].x);
            hpm[kk] = pack2(-hc[kk].y, hc[kk].y);
        }
        #pragma unroll
        for (int b = 0; b < B; b++) {
            ull au = ac[b];
            ull as = swap2(au);
            #pragma unroll
            for (int kk = 0; kk < 2; kk++) {
                acc[kk][b] = fma2(au, hxx[kk], acc[kk][b]);
                acc[kk][b] = fma2(as, hpm[kk], acc[kk][b]);
            }
        }
    }
    int xr = __brev(x) >> 25;
    #pragma unroll
    for (int kk = 0; kk < 2; kk++)
        #pragma unroll
        for (int b = 0; b < B; b++)
            rows[kk*8 + b][xr] = unpack2(acc[kk][b]);
    __syncthreads();
    // 16 inverse FFTs: per stage, thread handles 8 butterflies
    #pragma unroll
    for (int stage = 1; stage <= 7; stage++) {
        int half = 1 << (stage - 1);
        #pragma unroll
        for (int m = 0; m < 8; m++) {
            int l = x + 128*m;
            int r = l >> 6, j = l & 63;
            int p = j & (half - 1);
            int i0 = ((j >> (stage - 1)) << stage) + p;
            int i1 = i0 + half;
            float2 w = tws[p << (7 - stage)];
            float2 u = rows[r][i0], v0 = rows[r][i1];
            float2 v = make_float2(v0.x*w.x + v0.y*w.y, -v0.x*w.y + v0.y*w.x);
            rows[r][i0] = make_float2(u.x + v.x, u.y + v.y);
            rows[r][i1] = make_float2(u.x - v.x, u.y - v.y);
        }
        __syncthreads();
    }
    #pragma unroll
    for (int kk = 0; kk < 2; kk++)
        #pragma unroll
        for (int b = 0; b < B; b++)
            g_tmp[(((size_t)(b*CO + k0 + kk)) * NY + o) * NX + x] = rows[kk*8 + b][x];
}

// ---------------- pole factors E1/E2 + A1/A2 (launch 4) ----------------------
__global__ void k_fac(const float* __restrict__ wp1_re, const float* __restrict__ wp1_im,
                      const float* __restrict__ wp2_re, const float* __restrict__ wp2_im,
                      const float* __restrict__ ty, const float* __restrict__ tx) {
    int blk = blockIdx.x;
    int o   = threadIdx.x;
    if (blk < CI*CO*M1) {
        int ikp = blk;
        float wr = wp1_re[ikp], wi = wp1_im[ikp];
        float d = ty[1] - ty[0];
        float invnd = 1.0f / ((float)NY * d);
        float k = (o < NY/2) ? (float)o : (float)(o - NY);
        float lam = TWO_PI_F * k * invnd;
        float a = -wr, b = lam - wi;
        float inv = 1.0f / (a*a + b*b);
        g_A1[ikp*NY + o] = make_float2(a*inv, -b*inv);
        float t = ty[o];
        float e = expf(wr * t);
        float sn, cs; sincosf(wi * t, &sn, &cs);
        g_E1[ikp*NY + o] = make_float2(e*cs, e*sn);
    } else {
        int ikq = blk - CI*CO*M1;
        float wr = wp2_re[ikq], wi = wp2_im[ikq];
        float d = tx[1] - tx[0];
        float invnd = 1.0f / ((float)NX * d);
        float k = (o < NX/2) ? (float)o : (float)(o - NX);
        float lam = TWO_PI_F * k * invnd;
        float a = -wr, b = lam - wi;
        float inv = 1.0f / (a*a + b*b);
        g_A2[ikq*NX + o] = make_float2(a*inv, -b*inv);
        float t = tx[o];
        float e = expf(wr * t);
        float sn, cs; sincosf(wi * t, &sn, &cs);
        g_E2[ikq*NX + o] = make_float2(e*cs, e*sn);
    }
}

// ---------------- T2 (launch 5): o-tile 32, warp-broadcast B -----------------
#define T2_OT 32
#define T2_KC 40
#define T2_PITCH 129
#define T2_SMEM ((T2_OT + T2_KC) * T2_PITCH * sizeof(float2))
extern __shared__ float2 dynsm[];
__global__ void __launch_bounds__(256, 3) k_T2() {
    float2* alphaS = dynsm;
    float2* a2S    = dynsm + T2_OT*T2_PITCH;
    const ull* alphaU = (const ull*)alphaS;
    const ull* a2U    = (const ull*)a2S;
    int blk = blockIdx.x;
    int oq = blk & 3;
    int bi = blk >> 2;
    int i  = bi & 31;
    int o0 = oq * T2_OT;
    int t  = threadIdx.x;
    const float2* A = g_alpha + (size_t)bi * NY * NX + (size_t)o0 * NX;
    #pragma unroll 4
    for (int l = t; l < T2_OT*128; l += 256) {
        int o = l >> 7, x = l & 127;
        alphaS[o*T2_PITCH + x] = A[(size_t)o * NX + x];
    }
    int u = t >> 5, v = t & 31;
    #pragma unroll 1
    for (int c = 0; c < 4; c++) {
        int kq0 = c * T2_KC;
        __syncthreads();
        for (int l = t; l < T2_KC*128; l += 256) {
            int r = l >> 7, x = l & 127;
            a2S[r*T2_PITCH + x] = g_A2[(size_t)(i*CO*M2 + kq0 + r) * NX + x];
        }
        __syncthreads();
        ull accP[5], accQ[5];
        #pragma unroll
        for (int j = 0; j < 5; j++) {
            accP[j] = pack2(0.f, 0.f);
            accQ[j] = pack2(0.f, 0.f);
        }
        #pragma unroll 4
        for (int x = 0; x < 128; x++) {
            ull bv[5];
            #pragma unroll
            for (int j = 0; j < 5; j++)
                bv[j] = a2U[(u*5 + j)*T2_PITCH + x];
            ull av  = alphaU[v*T2_PITCH + x];
            ull asw = swap2(av);
            #pragma unroll
            for (int j = 0; j < 5; j++) {
                accP[j] = fma2(av,  bv[j], accP[j]);
                accQ[j] = fma2(asw, bv[j], accQ[j]);
            }
        }
        #pragma unroll
        for (int j = 0; j < 5; j++) {
            float2 p = unpack2(accP[j]);
            float2 q = unpack2(accQ[j]);
            g_T2[((size_t)bi * CO*M2 + kq0 + u*5 + j) * NY + o0 + v] =
                make_float2(p.x - p.y, q.x + q.y);
        }
    }
}

// ---------------- res2 (launch 6) -------------------------------------------
__global__ void k_res2(const float* __restrict__ wr_re, const float* __restrict__ wr_im) {
    int bk = blockIdx.x;
    int b = bk >> 5, k = bk & 31;
    int t = threadIdx.x;
    __shared__ float2 wrS[CI][M1*M2];
    for (int idx = t; idx < CI*M1*M2; idx += 128) {
        int i = idx / (M1*M2), pq = idx % (M1*M2);
        wrS[i][pq] = make_float2(wr_re[(i*CO + k)*M1*M2 + pq], wr_im[(i*CO + k)*M1*M2 + pq]);
    }
    __syncthreads();
    float2 acc[M1*M2];
    #pragma unroll
    for (int j = 0; j < M1*M2; j++) acc[j] = make_float2(0.f, 0.f);
    for (int i = 0; i < CI; i++) {
        float2 a1[M1], t2[M2];
        #pragma unroll
        for (int p = 0; p < M1; p++) a1[p] = g_A1[((i*CO + k)*M1 + p)*NY + t];
        #pragma unroll
        for (int q = 0; q < M2; q++) t2[q] = g_T2[(((size_t)(b*CI + i)*CO + k)*M2 + q)*NY + t];
        #pragma unroll
        for (int p = 0; p < M1; p++)
            #pragma unroll
            for (int q = 0; q < M2; q++) {
                float2 wa = cmul(wrS[i][p*M2 + q], a1[p]);
                acc[p*M2 + q] = cfma(wa, t2[q], acc[p*M2 + q]);
            }
    }
    #pragma unroll
    for (int j = 0; j < M1*M2; j++)
        #pragma unroll
        for (int off = 16; off; off >>= 1) {
            acc[j].x += __shfl_down_sync(0xffffffffu, acc[j].x, off);
            acc[j].y += __shfl_down_sync(0xffffffffu, acc[j].y, off);
        }
    __shared__ float2 red[4][M1*M2];
    int w = t >> 5, lane = t & 31;
    if (lane == 0) {
        #pragma unroll
        for (int j = 0; j < M1*M2; j++) red[w][j] = acc[j];
    }
    __syncthreads();
    if (t < M1*M2) {
        float2 s = red[0][t];
        #pragma unroll
        for (int w2 = 1; w2 < 4; w2++) { s.x += red[w2][t].x; s.y += red[w2][t].y; }
        g_res2[bk*M1*M2 + t] = s;
    }
}

// ---------------- inverse columns (launch 7) ---------------------------------
__global__ void k_ifft_cols_r(float* __restrict__ out) {
    __shared__ float2 tile[NY][17];
    __shared__ float2 tws[64];
    int t = threadIdx.x;
    make_tws(tws, t);
    int blk = blockIdx.x;
    int xt = blk & 7, img = blk >> 3;
    int x0 = xt * 16;
    int tg = t >> 4, tx = t & 15;
    const float2* base = g_tmp + (size_t)img * NY * NX + x0;
    #pragma unroll
    for (int c = 0; c < 16; c++) {
        int y = c * 8 + tg;
        tile[__brev(y) >> 25][tx] = base[(size_t)y * NX + tx];
    }
    fft_col<1>(tile, tg, tx, tws);
    __syncthreads();
    const float INV = 1.0f / (float)(NY * NX);
    float* ob = out + (size_t)img * NY * NX + x0;
    #pragma unroll
    for (int c = 0; c < 16; c++) {
        int y = c * 8 + tg;
        ob[(size_t)y * NX + tx] = tile[y][tx].x * INV;
    }
}

// ---------------- x2 with fused G (launch 8) ---------------------------------
#define X2_E1   (128*64)
#define X2_R2   (CI*M1*M2)
#define X2_GS   (16*66)
#define X2_ES   (16*129)
#define X2_SMEM ((X2_E1 + X2_R2 + X2_GS + X2_ES) * sizeof(float2))
__global__ void __launch_bounds__(256) k_x2(float* __restrict__ out) {
    float2* e1S = dynsm;                 // [c*4+p][64 zz]
    float2* r2S = e1S + X2_E1;           // [c][p*5+q]
    float2* Gs  = r2S + X2_R2;           // [16][66]
    float2* Es  = Gs + X2_GS;            // [16][129]
    int blk = blockIdx.x;
    int zh  = blk & 1;
    int bk  = blk >> 1;
    int b = bk >> 5, k = bk & 31;
    int z0 = zh * 64;
    int t = threadIdx.x;
    int u = t >> 5, v = t & 31;
    for (int l = t; l < X2_E1; l += 256) {
        int cp = l >> 6, zz = l & 63;
        e1S[l] = g_E1[(((cp >> 2)*CO + k)*M1 + (cp & 3))*NY + z0 + zz];
    }
    for (int l = t; l < X2_R2; l += 256)
        r2S[l] = g_res2[(b*CO + (l/20))*20 + (l%20)];
    ull acc[8][4];
    #pragma unroll
    for (int j = 0; j < 8; j++)
        #pragma unroll
        for (int m = 0; m < 4; m++) acc[j][m] = pack2(0.f, 0.f);
    for (int k0 = 0; k0 < CI*M2; k0 += 16) {
        __syncthreads();
        for (int l = t; l < 16*64; l += 256) {
            int r = l >> 6, zz = l & 63;
            int cq = k0 + r; int c = cq / M2, q = cq % M2;
            float2 g = make_float2(0.f, 0.f);
            #pragma unroll
            for (int p = 0; p < M1; p++)
                g = cfma(r2S[c*20 + p*M2 + q], e1S[(c*4 + p)*64 + zz], g);
            Gs[r*66 + zz] = g;
        }
        for (int l = t; l < 16*128; l += 256) {
            int r = l >> 7, xx = l & 127;
            int cq = k0 + r; int c = cq / M2, q = cq % M2;
            Es[r*129 + xx] = g_E2[((size_t)(c*CO + k)*M2 + q)*NX + xx];
        }
        __syncthreads();
        #pragma unroll
        for (int kk = 0; kk < 16; kk++) {
            ulonglong2 gp[4];
            const ulonglong2* gq = (const ulonglong2*)&Gs[kk*66 + u*8];
            #pragma unroll
            for (int jp = 0; jp < 4; jp++) gp[jp] = gq[jp];
            #pragma unroll
            for (int m = 0; m < 4; m++) {
                ull e = *(const ull*)&Es[kk*129 + v + 32*m];
                #pragma unroll
                for (int jp = 0; jp < 4; jp++) {
                    acc[2*jp  ][m] = fma2(gp[jp].x, e, acc[2*jp  ][m]);
                    acc[2*jp+1][m] = fma2(gp[jp].y, e, acc[2*jp+1][m]);
                }
            }
        }
    }
    const float INV = 1.0f / (float)(NY * NX);
    float* ob = out + (size_t)(b*CO + k) * NY * NX;
    #pragma unroll
    for (int j = 0; j < 8; j++) {
        int z = z0 + u*8 + j;
        #pragma unroll
        for (int m = 0; m < 4; m++) {
            float2 r = unpack2(acc[j][m]);
            ob[(size_t)z * NX + v + 32*m] += (r.x - r.y) * INV;
        }
    }
}

// ---------------------------------------------------------------------------
extern "C" void kernel_launch(void* const* d_in, const int* in_sizes, int n_in,
                              void* d_out, int out_size) {
    const float* x      = (const float*)d_in[0];
    const float* wp1_re = (const float*)d_in[1];
    const float* wp1_im = (const float*)d_in[2];
    const float* wp2_re = (const float*)d_in[3];
    const float* wp2_im = (const float*)d_in[4];
    const float* wr_re  = (const float*)d_in[5];
    const float* wr_im  = (const float*)d_in[6];
    const float* ty     = (const float*)d_in[7];
    const float* tx     = (const float*)d_in[8];
    float* out = (float*)d_out;

    cudaFuncSetAttribute(k_T2, cudaFuncAttributeMaxDynamicSharedMemorySize, (int)T2_SMEM);
    cudaFuncSetAttribute(k_x2, cudaFuncAttributeMaxDynamicSharedMemorySize, (int)X2_SMEM);

    k_hsum        <<<CI*CO, 128>>>(wp1_re, wp1_im, wp2_re, wp2_im, ty, tx, wr_re, wr_im); // 0
    k_fft_rows_f  <<<B*CI*NY/2, 128>>>(x);                                                // 1
    k_fft_cols_f  <<<B*CI*8, 128>>>();                                                    // 2
    k_res1f       <<<16*NY, 128>>>();                                                     // 3 (profiled)
    k_fac         <<<CI*CO*(M1+M2), 128>>>(wp1_re, wp1_im, wp2_re, wp2_im, ty, tx);       // 4
    k_T2          <<<B*CI*4, 256, T2_SMEM>>>();                                           // 5
    k_res2        <<<B*CO, 128>>>(wr_re, wr_im);                                          // 6
    k_ifft_cols_r <<<B*CO*8, 128>>>(out);                                                 // 7
    k_x2          <<<B*CO*2, 256, X2_SMEM>>>(out);                                        // 8
}

// round 12
// speedup vs baseline: 1.2403x; 1.0452x over previous
#include <cuda_runtime.h>

#define B   8
#define CI  32
#define CO  32
#define NY  128
#define NX  128
#define M1  4
#define M2  5

#define TWO_PI_F 6.283185307179586476925f

typedef unsigned long long ull;

__device__ __forceinline__ float2 cmul(float2 a, float2 b) {
    return make_float2(a.x*b.x - a.y*b.y, a.x*b.y + a.y*b.x);
}
__device__ __forceinline__ float2 cfma(float2 a, float2 b, float2 c) {
    c.x = fmaf(a.x, b.x, fmaf(-a.y, b.y, c.x));
    c.y = fmaf(a.x, b.y, fmaf( a.y, b.x, c.y));
    return c;
}
__device__ __forceinline__ ull pack2(float lo, float hi) {
    ull r; asm("mov.b64 %0, {%1, %2};" : "=l"(r) : "f"(lo), "f"(hi)); return r;
}
__device__ __forceinline__ float2 unpack2(ull v) {
    float2 f; asm("mov.b64 {%0, %1}, %2;" : "=f"(f.x), "=f"(f.y) : "l"(v)); return f;
}
__device__ __forceinline__ ull fma2(ull a, ull b, ull c) {
    ull d; asm("fma.rn.f32x2 %0, %1, %2, %3;" : "=l"(d) : "l"(a), "l"(b), "l"(c)); return d;
}
__device__ __forceinline__ ull swap2(ull a) {
    float2 f = unpack2(a);
    return pack2(f.y, f.x);
}

// ---------------- scratch ---------------------------------------------------
__device__ float2 g_tmp  [B*CI*NY*NX];
__device__ float2 g_alpha[B*CI*NY*NX];
__device__ float2 g_A1   [CI*CO*M1*NY];
__device__ float2 g_A2   [CI*CO*M2*NX];
__device__ float2 g_E1   [CI*CO*M1*NY];
__device__ float2 g_E2   [CI*CO*M2*NX];
__device__ float2 g_H    [CI*CO*NY*NX];
__device__ float2 g_S1   [B*CI*CO*M1*NX];
__device__ float2 g_res2 [B*CO*M1*M2];

__device__ __forceinline__ void make_tws(float2* tws, int t) {
    if (t < 64) {
        float sn, cs;
        sincospif(-(float)t / 64.f, &sn, &cs);
        tws[t] = make_float2(cs, sn);
    }
}

// ---------------- pole factors E1/E2 + A1/A2 (launch 0) ----------------------
__global__ void k_fac(const float* __restrict__ wp1_re, const float* __restrict__ wp1_im,
                      const float* __restrict__ wp2_re, const float* __restrict__ wp2_im,
                      const float* __restrict__ ty, const float* __restrict__ tx) {
    int blk = blockIdx.x;
    int o   = threadIdx.x;
    if (blk < CI*CO*M1) {
        int ikp = blk;
        float wr = wp1_re[ikp], wi = wp1_im[ikp];
        float d = ty[1] - ty[0];
        float invnd = 1.0f / ((float)NY * d);
        float k = (o < NY/2) ? (float)o : (float)(o - NY);
        float lam = TWO_PI_F * k * invnd;
        float a = -wr, b = lam - wi;
        float inv = 1.0f / (a*a + b*b);
        g_A1[ikp*NY + o] = make_float2(a*inv, -b*inv);
        float t = ty[o];
        float e = expf(wr * t);
        float sn, cs; sincosf(wi * t, &sn, &cs);
        g_E1[ikp*NY + o] = make_float2(e*cs, e*sn);
    } else {
        int ikq = blk - CI*CO*M1;
        float wr = wp2_re[ikq], wi = wp2_im[ikq];
        float d = tx[1] - tx[0];
        float invnd = 1.0f / ((float)NX * d);
        float k = (o < NX/2) ? (float)o : (float)(o - NX);
        float lam = TWO_PI_F * k * invnd;
        float a = -wr, b = lam - wi;
        float inv = 1.0f / (a*a + b*b);
        g_A2[ikq*NX + o] = make_float2(a*inv, -b*inv);
        float t = tx[o];
        float e = expf(wr * t);
        float sn, cs; sincosf(wi * t, &sn, &cs);
        g_E2[ikq*NX + o] = make_float2(e*cs, e*sn);
    }
}

// ---------------- 128-pt radix-2 DIT ----------------------------------------
template<int INV>
__device__ __forceinline__ void fft64th(float2* s, int tt, const float2* tws) {
    #pragma unroll
    for (int stage = 1; stage <= 7; stage++) {
        __syncthreads();
        int half = 1 << (stage - 1);
        int p  = tt & (half - 1);
        int i0 = ((tt >> (stage - 1)) << stage) + p;
        int i1 = i0 + half;
        float2 w = tws[p << (7 - stage)];
        float wy = INV ? -w.y : w.y;
        float2 u = s[i0], v0 = s[i1];
        float2 v = make_float2(v0.x*w.x - v0.y*wy, v0.x*wy + v0.y*w.x);
        s[i0] = make_float2(u.x + v.x, u.y + v.y);
        s[i1] = make_float2(u.x - v.x, u.y - v.y);
    }
}

// forward FFT of real rows (launch 1)
__global__ void k_fft_rows_f(const float* __restrict__ x) {
    __shared__ float2 s[2][NX];
    __shared__ float2 tws[64];
    int t = threadIdx.x, r = t >> 6, tt = t & 63;
    make_tws(tws, t);
    size_t row = (size_t)blockIdx.x * 2 + r;
    const float* xr = x + row * NX;
    s[r][tt]      = make_float2(xr[__brev(tt)      >> 25], 0.f);
    s[r][tt + 64] = make_float2(xr[__brev(tt + 64) >> 25], 0.f);
    fft64th<0>(s[r], tt, tws);
    float2* o = g_tmp + row * NX;
    o[tt] = s[r][tt]; o[tt + 64] = s[r][tt + 64];
}

template<int INV>
__device__ __forceinline__ void fft_col(float2 (*tile)[17], int tg, int tx, const float2* tws) {
    #pragma unroll
    for (int stage = 1; stage <= 7; stage++) {
        __syncthreads();
        int half = 1 << (stage - 1);
        #pragma unroll
        for (int m = 0; m < 8; m++) {
            int j  = tg + 8 * m;
            int p  = j & (half - 1);
            int i0 = ((j >> (stage - 1)) << stage) + p;
            int i1 = i0 + half;
            float2 w = tws[p << (7 - stage)];
            float wy = INV ? -w.y : w.y;
            float2 u = tile[i0][tx], v0 = tile[i1][tx];
            float2 v = make_float2(v0.x*w.x - v0.y*wy, v0.x*wy + v0.y*w.x);
            tile[i0][tx] = make_float2(u.x + v.x, u.y + v.y);
            tile[i1][tx] = make_float2(u.x - v.x, u.y - v.y);
        }
    }
}

// forward columns (launch 2): g_tmp -> g_alpha
__global__ void k_fft_cols_f() {
    __shared__ float2 tile[NY][17];
    __shared__ float2 tws[64];
    int t = threadIdx.x;
    make_tws(tws, t);
    int blk = blockIdx.x;
    int xt = blk & 7, img = blk >> 3;
    int x0 = xt * 16;
    int tg = t >> 4, tx = t & 15;
    const float2* base = g_tmp + (size_t)img * NY * NX + x0;
    #pragma unroll
    for (int c = 0; c < 16; c++) {
        int y = c * 8 + tg;
        tile[__brev(y) >> 25][tx] = base[(size_t)y * NX + tx];
    }
    fft_col<0>(tile, tg, tx, tws);
    __syncthreads();
    float2* ob = g_alpha + (size_t)img * NY * NX + x0;
    #pragma unroll
    for (int c = 0; c < 16; c++) {
        int y = c * 8 + tg;
        ob[(size_t)y * NX + tx] = tile[y][tx];
    }
}

// ---------------- S1[b,i,kp,x] = sum_o A1[i,kp,o] * alpha[b,i,o,x] (launch 3)
// o-first contraction (M1=4): 537M cmul vs old T2's 671M.
// Block: (b,i) x xh(2). alphaS [128 o][64 x] pitch 64; A1S chunk [32 kp][128 o].
// Warp u -> kp group of 4 (broadcast), lanes -> x, Jx=2 (v, v+32).
#define S1_XT 64
#define S1_KC 32
#define S1_SMEM ((128*S1_XT + S1_KC*128) * sizeof(float2))
extern __shared__ float2 dynsm[];
__global__ void __launch_bounds__(256, 2) k_S1() {
    float2* alphaS = dynsm;                  // [128 o][64 x]
    float2* a1S    = dynsm + 128*S1_XT;      // [32 kp][128 o]
    const ull* alphaU = (const ull*)alphaS;
    const ull* a1U    = (const ull*)a1S;
    int blk = blockIdx.x;
    int xh = blk & 1;
    int bi = blk >> 1;
    int i  = bi & 31;
    int x0 = xh * S1_XT;
    int t  = threadIdx.x;
    // load alpha half-image [128 o][64 x] (coalesced 512B rows)
    const float2* A = g_alpha + (size_t)bi * NY * NX + x0;
    #pragma unroll 4
    for (int l = t; l < 128*S1_XT; l += 256) {
        int o = l >> 6, xi = l & 63;
        alphaS[(o << 6) + xi] = A[(size_t)o * NX + xi];
    }
    int u = t >> 5, v = t & 31;
    #pragma unroll 1
    for (int c = 0; c < 4; c++) {
        int kp0 = c * S1_KC;
        __syncthreads();
        for (int l = t; l < S1_KC*128; l += 256) {
            int r = l >> 7, o = l & 127;
            a1S[(r << 7) + o] = g_A1[((size_t)i*CO*M1 + kp0 + r) * NY + o];
        }
        __syncthreads();
        ull accP[4][2], accQ[4][2];
        #pragma unroll
        for (int j = 0; j < 4; j++)
            #pragma unroll
            for (int m = 0; m < 2; m++) {
                accP[j][m] = pack2(0.f, 0.f);
                accQ[j][m] = pack2(0.f, 0.f);
            }
        #pragma unroll 4
        for (int o = 0; o < 128; o++) {
            ull bv[4];
            #pragma unroll
            for (int j = 0; j < 4; j++)
                bv[j] = a1U[((u*4 + j) << 7) + o];       // warp-broadcast
            ull a0 = alphaU[(o << 6) + v];
            ull a1 = alphaU[(o << 6) + v + 32];
            ull s0 = swap2(a0), s1 = swap2(a1);
            #pragma unroll
            for (int j = 0; j < 4; j++) {
                accP[j][0] = fma2(a0, bv[j], accP[j][0]);
                accQ[j][0] = fma2(s0, bv[j], accQ[j][0]);
                accP[j][1] = fma2(a1, bv[j], accP[j][1]);
                accQ[j][1] = fma2(s1, bv[j], accQ[j][1]);
            }
        }
        #pragma unroll
        for (int j = 0; j < 4; j++) {
            float2* dst = g_S1 + ((size_t)bi * CO*M1 + kp0 + u*4 + j) * NX + x0;
            #pragma unroll
            for (int m = 0; m < 2; m++) {
                float2 p = unpack2(accP[j][m]);
                float2 q = unpack2(accQ[j][m]);
                dst[v + 32*m] = make_float2(p.x - p.y, q.x + q.y);
            }
        }
    }
}

// ---------------- Hsum with inline A1/A2 (launch 4) --------------------------
__global__ void k_hsum(const float* __restrict__ wp1_re, const float* __restrict__ wp1_im,
                       const float* __restrict__ wp2_re, const float* __restrict__ wp2_im,
                       const float* __restrict__ ty, const float* __restrict__ tx,
                       const float* __restrict__ wr_re, const float* __restrict__ wr_im) {
    int ik = blockIdx.x;
    int t  = threadIdx.x;
    __shared__ float2 wrS[M1*M2];
    __shared__ float2 A1S[M1][NY];
    __shared__ float2 U[M2][NY];
    if (t < M1*M2) wrS[t] = make_float2(wr_re[ik*M1*M2 + t], wr_im[ik*M1*M2 + t]);
    float kf = (t < NY/2) ? (float)t : (float)(t - NY);
    {
        float d = ty[1] - ty[0];
        float invnd = 1.0f / ((float)NY * d);
        float lam = TWO_PI_F * kf * invnd;
        #pragma unroll
        for (int p = 0; p < M1; p++) {
            float wr = wp1_re[ik*M1 + p], wi = wp1_im[ik*M1 + p];
            float a = -wr, b = lam - wi;
            float inv = 1.0f / (a*a + b*b);
            A1S[p][t] = make_float2(a*inv, -b*inv);
        }
    }
    float2 a2[M2];
    {
        float d = tx[1] - tx[0];
        float invnd = 1.0f / ((float)NX * d);
        float lam = TWO_PI_F * kf * invnd;
        #pragma unroll
        for (int q = 0; q < M2; q++) {
            float wr = wp2_re[ik*M2 + q], wi = wp2_im[ik*M2 + q];
            float a = -wr, b = lam - wi;
            float inv = 1.0f / (a*a + b*b);
            a2[q] = make_float2(a*inv, -b*inv);
        }
    }
    __syncthreads();
    #pragma unroll
    for (int q = 0; q < M2; q++) {
        float2 acc = make_float2(0.f, 0.f);
        #pragma unroll
        for (int p = 0; p < M1; p++) acc = cfma(wrS[p*M2 + q], A1S[p][t], acc);
        U[q][t] = acc;
    }
    __syncthreads();
    float2* H = g_H + (size_t)ik * NY * NX;
    for (int o = 0; o < NY; o++) {
        float2 acc = make_float2(0.f, 0.f);
        #pragma unroll
        for (int q = 0; q < M2; q++) acc = cfma(U[q][o], a2[q], acc);
        __stcs(&H[o*NX + t], acc);
    }
}

// ---------------- res2[b,k,p,q] = sum_i wr * sum_x S1[p,x]*A2[q,x] (launch 5)
__global__ void k_res2(const float* __restrict__ wr_re, const float* __restrict__ wr_im) {
    int bk = blockIdx.x;
    int b = bk >> 5, k = bk & 31;
    int t = threadIdx.x;                  // x
    __shared__ float2 wrS[CI][M1*M2];
    for (int idx = t; idx < CI*M1*M2; idx += 128) {
        int i = idx / (M1*M2), pq = idx % (M1*M2);
        wrS[i][pq] = make_float2(wr_re[(i*CO + k)*M1*M2 + pq], wr_im[(i*CO + k)*M1*M2 + pq]);
    }
    __syncthreads();
    float2 acc[M1*M2];
    #pragma unroll
    for (int j = 0; j < M1*M2; j++) acc[j] = make_float2(0.f, 0.f);
    for (int i = 0; i < CI; i++) {
        float2 s1[M1], a2[M2];
        #pragma unroll
        for (int p = 0; p < M1; p++)
            s1[p] = g_S1[((size_t)(b*CI + i)*CO*M1 + k*M1 + p)*NX + t];
        #pragma unroll
        for (int q = 0; q < M2; q++)
            a2[q] = g_A2[((size_t)(i*CO + k)*M2 + q)*NX + t];
        #pragma unroll
        for (int p = 0; p < M1; p++)
            #pragma unroll
            for (int q = 0; q < M2; q++) {
                float2 wa = cmul(wrS[i][p*M2 + q], s1[p]);
                acc[p*M2 + q] = cfma(wa, a2[q], acc[p*M2 + q]);
            }
    }
    #pragma unroll
    for (int j = 0; j < M1*M2; j++)
        #pragma unroll
        for (int off = 16; off; off >>= 1) {
            acc[j].x += __shfl_down_sync(0xffffffffu, acc[j].x, off);
            acc[j].y += __shfl_down_sync(0xffffffffu, acc[j].y, off);
        }
    __shared__ float2 red[4][M1*M2];
    int w = t >> 5, lane = t & 31;
    if (lane == 0) {
        #pragma unroll
        for (int j = 0; j < M1*M2; j++) red[w][j] = acc[j];
    }
    __syncthreads();
    if (t < M1*M2) {
        float2 s = red[0][t];
        #pragma unroll
        for (int w2 = 1; w2 < 4; w2++) { s.x += red[w2][t].x; s.y += red[w2][t].y; }
        g_res2[bk*M1*M2 + t] = s;
    }
}

// ---------------- res1 + inverse row FFT, k-tile 2 (launch 6) ----------------
__global__ void __launch_bounds__(128, 5) k_res1f() {
    __shared__ float2 rows[16][129];
    __shared__ float2 tws[64];
    int o  = blockIdx.x & 127;
    int k0 = (blockIdx.x >> 7) * 2;
    int x  = threadIdx.x;
    make_tws(tws, x);
    const ull* alphaU = (const ull*)g_alpha;
    ull acc[2][B];
    #pragma unroll
    for (int kk = 0; kk < 2; kk++)
        #pragma unroll
        for (int b = 0; b < B; b++) acc[kk][b] = pack2(0.f, 0.f);

    for (int i = 0; i < CI; i++) {
        float2 hc[2];
        #pragma unroll
        for (int kk = 0; kk < 2; kk++)
            hc[kk] = __ldcs(&g_H[((size_t)(i*CO + k0 + kk) * NY + o) * NX + x]);
        ull ac[8];
        #pragma unroll
        for (int b = 0; b < B; b++)
            ac[b] = alphaU[((size_t)(b*CI + i) * NY + o) * NX + x];
        ull hxx[2], hpm[2];
        #pragma unroll
        for (int kk = 0; kk < 2; kk++) {
            hxx[kk] = pack2(hc[kk].x,  hc[kk].x);
            hpm[kk] = pack2(-hc[kk].y, hc[kk].y);
        }
        #pragma unroll
        for (int b = 0; b < B; b++) {
            ull au = ac[b];
            ull as = swap2(au);
            #pragma unroll
            for (int kk = 0; kk < 2; kk++) {
                acc[kk][b] = fma2(au, hxx[kk], acc[kk][b]);
                acc[kk][b] = fma2(as, hpm[kk], acc[kk][b]);
            }
        }
    }
    int xr = __brev(x) >> 25;
    #pragma unroll
    for (int kk = 0; kk < 2; kk++)
        #pragma unroll
        for (int b = 0; b < B; b++)
            rows[kk*8 + b][xr] = unpack2(acc[kk][b]);
    __syncthreads();
    #pragma unroll
    for (int stage = 1; stage <= 7; stage++) {
        int half = 1 << (stage - 1);
        #pragma unroll
        for (int m = 0; m < 8; m++) {
            int l = x + 128*m;
            int r = l >> 6, j = l & 63;
            int p = j & (half - 1);
            int i0 = ((j >> (stage - 1)) << stage) + p;
            int i1 = i0 + half;
            float2 w = tws[p << (7 - stage)];
            float2 u = rows[r][i0], v0 = rows[r][i1];
            float2 v = make_float2(v0.x*w.x + v0.y*w.y, -v0.x*w.y + v0.y*w.x);
            rows[r][i0] = make_float2(u.x + v.x, u.y + v.y);
            rows[r][i1] = make_float2(u.x - v.x, u.y - v.y);
        }
        __syncthreads();
    }
    #pragma unroll
    for (int kk = 0; kk < 2; kk++)
        #pragma unroll
        for (int b = 0; b < B; b++)
            g_tmp[(((size_t)(b*CO + k0 + kk)) * NY + o) * NX + x] = rows[kk*8 + b][x];
}

// ---------------- inverse columns (launch 7) ---------------------------------
__global__ void k_ifft_cols_r(float* __restrict__ out) {
    __shared__ float2 tile[NY][17];
    __shared__ float2 tws[64];
    int t = threadIdx.x;
    make_tws(tws, t);
    int blk = blockIdx.x;
    int xt = blk & 7, img = blk >> 3;
    int x0 = xt * 16;
    int tg = t >> 4, tx = t & 15;
    const float2* base = g_tmp + (size_t)img * NY * NX + x0;
    #pragma unroll
    for (int c = 0; c < 16; c++) {
        int y = c * 8 + tg;
        tile[__brev(y) >> 25][tx] = base[(size_t)y * NX + tx];
    }
    fft_col<1>(tile, tg, tx, tws);
    __syncthreads();
    const float INV = 1.0f / (float)(NY * NX);
    float* ob = out + (size_t)img * NY * NX + x0;
    #pragma unroll
    for (int c = 0; c < 16; c++) {
        int y = c * 8 + tg;
        ob[(size_t)y * NX + tx] = tile[y][tx].x * INV;
    }
}

// ---------------- x2 with fused G (launch 8) ---------------------------------
#define X2_E1   (128*64)
#define X2_R2   (CI*M1*M2)
#define X2_GS   (16*66)
#define X2_ES   (16*129)
#define X2_SMEM ((X2_E1 + X2_R2 + X2_GS + X2_ES) * sizeof(float2))
__global__ void __launch_bounds__(256) k_x2(float* __restrict__ out) {
    float2* e1S = dynsm;                 // [c*4+p][64 zz]
    float2* r2S = e1S + X2_E1;           // [c][p*5+q]
    float2* Gs  = r2S + X2_R2;           // [16][66]
    float2* Es  = Gs + X2_GS;            // [16][129]
    int blk = blockIdx.x;
    int zh  = blk & 1;
    int bk  = blk >> 1;
    int b = bk >> 5, k = bk & 31;
    int z0 = zh * 64;
    int t = threadIdx.x;
    int u = t >> 5, v = t & 31;
    for (int l = t; l < X2_E1; l += 256) {
        int cp = l >> 6, zz = l & 63;
        e1S[l] = g_E1[(((cp >> 2)*CO + k)*M1 + (cp & 3))*NY + z0 + zz];
    }
    for (int l = t; l < X2_R2; l += 256)
        r2S[l] = g_res2[(b*CO + (l/20))*20 + (l%20)];
    ull acc[8][4];
    #pragma unroll
    for (int j = 0; j < 8; j++)
        #pragma unroll
        for (int m = 0; m < 4; m++) acc[j][m] = pack2(0.f, 0.f);
    for (int k0 = 0; k0 < CI*M2; k0 += 16) {
        __syncthreads();
        for (int l = t; l < 16*64; l += 256) {
            int r = l >> 6, zz = l & 63;
            int cq = k0 + r; int c = cq / M2, q = cq % M2;
            float2 g = make_float2(0.f, 0.f);
            #pragma unroll
            for (int p = 0; p < M1; p++)
                g = cfma(r2S[c*20 + p*M2 + q], e1S[(c*4 + p)*64 + zz], g);
            Gs[r*66 + zz] = g;
        }
        for (int l = t; l < 16*128; l += 256) {
            int r = l >> 7, xx = l & 127;
            int cq = k0 + r; int c = cq / M2, q = cq % M2;
            Es[r*129 + xx] = g_E2[((size_t)(c*CO + k)*M2 + q)*NX + xx];
        }
        __syncthreads();
        #pragma unroll
        for (int kk = 0; kk < 16; kk++) {
            ulonglong2 gp[4];
            const ulonglong2* gq = (const ulonglong2*)&Gs[kk*66 + u*8];
            #pragma unroll
            for (int jp = 0; jp < 4; jp++) gp[jp] = gq[jp];
            #pragma unroll
            for (int m = 0; m < 4; m++) {
                ull e = *(const ull*)&Es[kk*129 + v + 32*m];
                #pragma unroll
                for (int jp = 0; jp < 4; jp++) {
                    acc[2*jp  ][m] = fma2(gp[jp].x, e, acc[2*jp  ][m]);
                    acc[2*jp+1][m] = fma2(gp[jp].y, e, acc[2*jp+1][m]);
                }
            }
        }
    }
    const float INV = 1.0f / (float)(NY * NX);
    float* ob = out + (size_t)(b*CO + k) * NY * NX;
    #pragma unroll
    for (int j = 0; j < 8; j++) {
        int z = z0 + u*8 + j;
        #pragma unroll
        for (int m = 0; m < 4; m++) {
            float2 r = unpack2(acc[j][m]);
            ob[(size_t)z * NX + v + 32*m] += (r.x - r.y) * INV;
        }
    }
}

// ---------------------------------------------------------------------------
extern "C" void kernel_launch(void* const* d_in, const int* in_sizes, int n_in,
                              void* d_out, int out_size) {
    const float* x      = (const float*)d_in[0];
    const float* wp1_re = (const float*)d_in[1];
    const float* wp1_im = (const float*)d_in[2];
    const float* wp2_re = (const float*)d_in[3];
    const float* wp2_im = (const float*)d_in[4];
    const float* wr_re  = (const float*)d_in[5];
    const float* wr_im  = (const float*)d_in[6];
    const float* ty     = (const float*)d_in[7];
    const float* tx     = (const float*)d_in[8];
    float* out = (float*)d_out;

    cudaFuncSetAttribute(k_S1, cudaFuncAttributeMaxDynamicSharedMemorySize, (int)S1_SMEM);
    cudaFuncSetAttribute(k_x2, cudaFuncAttributeMaxDynamicSharedMemorySize, (int)X2_SMEM);

    k_fac         <<<CI*CO*(M1+M2), 128>>>(wp1_re, wp1_im, wp2_re, wp2_im, ty, tx);       // 0
    k_fft_rows_f  <<<B*CI*NY/2, 128>>>(x);                                                // 1
    k_fft_cols_f  <<<B*CI*8, 128>>>();                                                    // 2
    k_S1          <<<B*CI*2, 256, S1_SMEM>>>();                                           // 3 (profiled)
    k_hsum        <<<CI*CO, 128>>>(wp1_re, wp1_im, wp2_re, wp2_im, ty, tx, wr_re, wr_im); // 4
    k_res2        <<<B*CO, 128>>>(wr_re, wr_im);                                          // 5
    k_res1f       <<<16*NY, 128>>>();                                                     // 6
    k_ifft_cols_r <<<B*CO*8, 128>>>(out);                                                 // 7
    k_x2          <<<B*CO*2, 256, X2_SMEM>>>(out);                                        // 8
}